// round 7
// baseline (speedup 1.0000x reference)
#include <cuda_runtime.h>
#include <cuda_bf16.h>
#include <cuda_fp16.h>
#include <math.h>

#define NN 65536
#define NE 524288
#define EX (NE + NN)
#define DD 128
#define PK 136   // padded k-dim (bf16 elems); 272B rows => ldmatrix conflict-free

// ---------------- scratch (device globals: allocation-free) ----------------
__device__ __half g_hh[(size_t)NN * DD];    // 16MB: h in fp16 (agg gather path)
__device__ float g_x[(size_t)NN * DD];      // 32MB: layer activations
__device__ float g_as[NN];
__device__ float g_ad[NN];
__device__ float g_rden[NN];
__device__ float g_ess[3][EX];              // edge scores; overwritten by weights in k_att
__device__ float g_essum[3][NN];
__device__ int   g_srcs[EX];
__device__ int   g_rowptr[NN + 1];
__device__ int   g_wslot[NN];
__device__ int   g_cnt[NN];
__device__ int   g_bsum[256];
__device__ float g_ve[3][32];
__device__ __nv_bfloat16 g_wh[3][DD * DD];   // W^T split hi (n-major)
__device__ __nv_bfloat16 g_wl[3][DD * DD];   // W^T split lo (n-major)

__device__ __forceinline__ float gelu_f(float x) {
    return 0.5f * x * (1.0f + erff(x * 0.7071067811865476f));
}

// ---------------- preprocessing ----------------
// blocks 0..191: split W -> bf16 hi/lo (transposed, n-major)
// block 192:     ve[l] = We[l] @ att_edge[l]
// blocks 193..448: zero cnt/essum
__global__ void k_wsplit(const float* __restrict__ Ws,
                         const float* __restrict__ We, const float* __restrict__ ae) {
    int b = blockIdx.x;
    if (b >= 193) {
        int i = (b - 193) * 256 + threadIdx.x;
        if (i < NN) {
            g_cnt[i] = 0;
            g_essum[0][i] = 0.f; g_essum[1][i] = 0.f; g_essum[2][i] = 0.f;
        }
        return;
    }
    if (b == 192) {
        int t = threadIdx.x;
        if (t < 96) {
            int l = t / 32, k = t % 32;
            const float* w = We + l * 32 * DD + k * DD;
            const float* a = ae + l * DD;
            float s = 0.f;
            #pragma unroll 8
            for (int d = 0; d < DD; d++) s += w[d] * a[d];
            g_ve[l][k] = s;
        }
        return;
    }
    int idx = b * blockDim.x + threadIdx.x;   // 3*128*128
    int l = idx >> 14;
    int rem = idx & 16383;
    int k = rem >> 7, n = rem & 127;
    float v = Ws[idx];
    __nv_bfloat16 h = __float2bfloat16_rn(v);
    float lo = v - __bfloat162float(h);
    g_wh[l][n * DD + k] = h;
    g_wl[l][n * DD + k] = __float2bfloat16_rn(lo);
}

__global__ void k_hist(const int* __restrict__ ei) {
    int e = blockIdx.x * blockDim.x + threadIdx.x;
    if (e < NE) atomicAdd(&g_cnt[ei[NE + e]], 1);
}

__global__ void k_bsum() {
    int b = blockIdx.x, t = threadIdx.x;
    int v = g_cnt[b * 256 + t] + 1;
    #pragma unroll
    for (int o = 16; o; o >>= 1) v += __shfl_xor_sync(0xffffffffu, v, o);
    __shared__ int ws[8];
    if ((t & 31) == 0) ws[t >> 5] = v;
    __syncthreads();
    if (t < 8) {
        int s = ws[t];
        #pragma unroll
        for (int o = 4; o; o >>= 1) s += __shfl_xor_sync(0xffu, s, o);
        if (t == 0) g_bsum[b] = s;
    }
}

__global__ void k_bscan() {
    int t = threadIdx.x;
    int lane = t & 31, w = t >> 5;
    int v = g_bsum[t];
    int x = v;
    #pragma unroll
    for (int o = 1; o < 32; o <<= 1) {
        int y = __shfl_up_sync(0xffffffffu, x, o);
        if (lane >= o) x += y;
    }
    __shared__ int ws[8];
    if (lane == 31) ws[w] = x;
    __syncthreads();
    if (t < 8) {
        int s = ws[t];
        #pragma unroll
        for (int o = 1; o < 8; o <<= 1) {
            int y = __shfl_up_sync(0xffu, s, o);
            if (t >= o) s += y;
        }
        ws[t] = s;
    }
    __syncthreads();
    int incl = x + (w ? ws[w - 1] : 0);
    g_bsum[t] = incl - v;
    if (t == 255) g_rowptr[NN] = EX;
}

__global__ void k_rowptr() {
    int b = blockIdx.x, t = threadIdx.x;
    int n = b * 256 + t;
    int lane = t & 31, w = t >> 5;
    int v = g_cnt[n] + 1;
    int x = v;
    #pragma unroll
    for (int o = 1; o < 32; o <<= 1) {
        int y = __shfl_up_sync(0xffffffffu, x, o);
        if (lane >= o) x += y;
    }
    __shared__ int ws[8];
    if (lane == 31) ws[w] = x;
    __syncthreads();
    if (t < 8) {
        int s = ws[t];
        #pragma unroll
        for (int o = 1; o < 8; o <<= 1) {
            int y = __shfl_up_sync(0xffu, s, o);
            if (t >= o) s += y;
        }
        ws[t] = s;
    }
    __syncthreads();
    int excl = x - v + (w ? ws[w - 1] : 0) + g_bsum[b];
    g_rowptr[n] = excl;
    g_wslot[n] = excl;
}

__global__ void k_scatter(const int* __restrict__ ei, const float* __restrict__ ea) {
    __shared__ float sve[96];
    if (threadIdx.x < 96) sve[threadIdx.x] = ((const float*)g_ve)[threadIdx.x];
    __syncthreads();
    int e = blockIdx.x * blockDim.x + threadIdx.x;
    if (e >= NE) return;
    int s = ei[e];
    int d = ei[NE + e];
    const float4* a4 = (const float4*)(ea + (size_t)e * 32);
    float dot0 = 0.f, dot1 = 0.f, dot2 = 0.f;
    #pragma unroll
    for (int q = 0; q < 8; q++) {
        float4 v = a4[q];
        const float* v0 = sve + 0 * 32 + q * 4;
        const float* v1 = sve + 1 * 32 + q * 4;
        const float* v2 = sve + 2 * 32 + q * 4;
        dot0 += v.x * v0[0] + v.y * v0[1] + v.z * v0[2] + v.w * v0[3];
        dot1 += v.x * v1[0] + v.y * v1[1] + v.z * v1[2] + v.w * v1[3];
        dot2 += v.x * v2[0] + v.y * v2[1] + v.z * v2[2] + v.w * v2[3];
    }
    int p = atomicAdd(&g_wslot[d], 1);
    g_srcs[p] = s;
    g_ess[0][p] = dot0; g_ess[1][p] = dot1; g_ess[2][p] = dot2;
    atomicAdd(&g_essum[0][d], dot0);
    atomicAdd(&g_essum[1][d], dot1);
    atomicAdd(&g_essum[2][d], dot2);
}

__global__ void k_selfloop() {
    int n = blockIdx.x * blockDim.x + threadIdx.x;
    if (n >= NN) return;
    int pos = g_rowptr[n + 1] - 1;
    g_srcs[pos] = n;
    float cf = fmaxf((float)g_cnt[n], 1.0f);
    g_ess[0][pos] = g_essum[0][n] / cf;
    g_ess[1][pos] = g_essum[1][n] / cf;
    g_ess[2][pos] = g_essum[2][n] / cf;
}

// ---------------- tensor-core GEMM + fused rowdots, fp16 h output ----------------
__device__ __forceinline__ void mma16816(float* c, const unsigned* a, const unsigned* b) {
    asm volatile(
        "mma.sync.aligned.m16n8k16.row.col.f32.bf16.bf16.f32 "
        "{%0,%1,%2,%3},{%4,%5,%6,%7},{%8,%9},{%0,%1,%2,%3};\n"
        : "+f"(c[0]), "+f"(c[1]), "+f"(c[2]), "+f"(c[3])
        : "r"(a[0]), "r"(a[1]), "r"(a[2]), "r"(a[3]), "r"(b[0]), "r"(b[1]));
}

__device__ __forceinline__ void ldm_x4(unsigned* r, unsigned addr) {
    asm volatile("ldmatrix.sync.aligned.m8n8.x4.shared.b16 {%0,%1,%2,%3},[%4];"
                 : "=r"(r[0]), "=r"(r[1]), "=r"(r[2]), "=r"(r[3]) : "r"(addr));
}

__device__ __forceinline__ void ldm_x2(unsigned* r, unsigned addr) {
    asm volatile("ldmatrix.sync.aligned.m8n8.x2.shared.b16 {%0,%1},[%2];"
                 : "=r"(r[0]), "=r"(r[1]) : "r"(addr));
}

extern __shared__ char smem_raw[];

__global__ void __launch_bounds__(256) k_gemm_tc(const float* __restrict__ Ain, int l,
                                                 const float* __restrict__ a_s,
                                                 const float* __restrict__ a_d) {
    const float* A = Ain ? Ain : g_x;
    __nv_bfloat16* sAh = (__nv_bfloat16*)smem_raw;
    __nv_bfloat16* sAl = sAh + 128 * PK;
    __nv_bfloat16* sBh = sAl + 128 * PK;
    __nv_bfloat16* sBl = sBh + 128 * PK;

    int tid = threadIdx.x;
    int row0 = blockIdx.x * 128;

    {
        const float4* A4 = (const float4*)(A + (size_t)row0 * DD);
        #pragma unroll
        for (int it = 0; it < 16; it++) {
            int idx = it * 256 + tid;
            int r = idx >> 5;
            int c = (idx & 31) << 2;
            float4 v = A4[idx];
            __nv_bfloat16 h0 = __float2bfloat16_rn(v.x), h1 = __float2bfloat16_rn(v.y);
            __nv_bfloat16 h2 = __float2bfloat16_rn(v.z), h3 = __float2bfloat16_rn(v.w);
            __nv_bfloat162 ha, hb, la, lb;
            ha.x = h0; ha.y = h1; hb.x = h2; hb.y = h3;
            la = __floats2bfloat162_rn(v.x - __bfloat162float(h0), v.y - __bfloat162float(h1));
            lb = __floats2bfloat162_rn(v.z - __bfloat162float(h2), v.w - __bfloat162float(h3));
            unsigned* dh = (unsigned*)(sAh + r * PK + c);
            unsigned* dl = (unsigned*)(sAl + r * PK + c);
            dh[0] = *(unsigned*)&ha; dh[1] = *(unsigned*)&hb;
            dl[0] = *(unsigned*)&la; dl[1] = *(unsigned*)&lb;
        }
    }
    {
        const uint4* wh4 = (const uint4*)g_wh[l];
        const uint4* wl4 = (const uint4*)g_wl[l];
        #pragma unroll
        for (int it = 0; it < 8; it++) {
            int idx = it * 256 + tid;
            int n = idx >> 4;
            int kc = idx & 15;
            ((uint4*)(sBh + n * PK))[kc] = wh4[idx];
            ((uint4*)(sBl + n * PK))[kc] = wl4[idx];
        }
    }
    __syncthreads();

    int wid = tid >> 5, lane = tid & 31;
    int g = lane >> 2, tq = lane & 3;
    int wm = wid >> 2, wn = wid & 3;
    int mbase = wm * 64, nbase = wn * 32;

    unsigned baseAh, baseAl, baseBh, baseBl;
    {
        int aoff = ((mbase + (lane & 15)) * PK + ((lane >> 4) << 3)) * 2;
        baseAh = (unsigned)__cvta_generic_to_shared(sAh) + aoff;
        baseAl = (unsigned)__cvta_generic_to_shared(sAl) + aoff;
        int boff = ((nbase + (lane & 7)) * PK + (((lane >> 3) & 1) << 3)) * 2;
        baseBh = (unsigned)__cvta_generic_to_shared(sBh) + boff;
        baseBl = (unsigned)__cvta_generic_to_shared(sBl) + boff;
    }

    float acc[4][4][4];
    #pragma unroll
    for (int i = 0; i < 4; i++)
        #pragma unroll
        for (int j = 0; j < 4; j++)
            #pragma unroll
            for (int q = 0; q < 4; q++) acc[i][j][q] = 0.f;

    #pragma unroll
    for (int kk = 0; kk < 8; kk++) {
        unsigned kb = kk * 32;
        unsigned Ah[4][4], Al[4][4], Bh[4][2], Bl[4][2];
        #pragma unroll
        for (int i = 0; i < 4; i++) {
            unsigned off = (unsigned)(i * 16 * PK * 2) + kb;
            ldm_x4(Ah[i], baseAh + off);
            ldm_x4(Al[i], baseAl + off);
        }
        #pragma unroll
        for (int j = 0; j < 4; j++) {
            unsigned off = (unsigned)(j * 8 * PK * 2) + kb;
            ldm_x2(Bh[j], baseBh + off);
            ldm_x2(Bl[j], baseBl + off);
        }
        #pragma unroll
        for (int i = 0; i < 4; i++)
            #pragma unroll
            for (int j = 0; j < 4; j++) {
                mma16816(acc[i][j], Ah[i], Bh[j]);
                mma16816(acc[i][j], Al[i], Bh[j]);
                mma16816(acc[i][j], Ah[i], Bl[j]);
            }
    }

    // store h as fp16
    #pragma unroll
    for (int i = 0; i < 4; i++) {
        int r = row0 + mbase + i * 16 + g;
        #pragma unroll
        for (int j = 0; j < 4; j++) {
            int c = nbase + j * 8 + 2 * tq;
            *(__half2*)(g_hh + (size_t)r * DD + c) =
                __float22half2_rn(make_float2(acc[i][j][0], acc[i][j][1]));
            *(__half2*)(g_hh + (size_t)(r + 8) * DD + c) =
                __float22half2_rn(make_float2(acc[i][j][2], acc[i][j][3]));
        }
    }

    // fused rowdots
    float asv[4][2], adv[4][2];
    #pragma unroll
    for (int j = 0; j < 4; j++) {
        int c = nbase + j * 8 + 2 * tq;
        asv[j][0] = a_s[c]; asv[j][1] = a_s[c + 1];
        adv[j][0] = a_d[c]; adv[j][1] = a_d[c + 1];
    }
    __syncthreads();
    float* s_red = (float*)smem_raw;
    if (tid < 128) { s_red[tid] = 0.f; s_red[128 + tid] = 0.f; }
    __syncthreads();
    #pragma unroll
    for (int i = 0; i < 4; i++) {
        float ps0 = 0.f, pd0 = 0.f, ps1 = 0.f, pd1 = 0.f;
        #pragma unroll
        for (int j = 0; j < 4; j++) {
            ps0 += acc[i][j][0] * asv[j][0] + acc[i][j][1] * asv[j][1];
            pd0 += acc[i][j][0] * adv[j][0] + acc[i][j][1] * adv[j][1];
            ps1 += acc[i][j][2] * asv[j][0] + acc[i][j][3] * asv[j][1];
            pd1 += acc[i][j][2] * adv[j][0] + acc[i][j][3] * adv[j][1];
        }
        #pragma unroll
        for (int o = 1; o < 4; o <<= 1) {
            ps0 += __shfl_xor_sync(0xffffffffu, ps0, o);
            pd0 += __shfl_xor_sync(0xffffffffu, pd0, o);
            ps1 += __shfl_xor_sync(0xffffffffu, ps1, o);
            pd1 += __shfl_xor_sync(0xffffffffu, pd1, o);
        }
        if (tq == 0) {
            int rl = mbase + i * 16 + g;
            atomicAdd(&s_red[rl], ps0);
            atomicAdd(&s_red[128 + rl], pd0);
            atomicAdd(&s_red[rl + 8], ps1);
            atomicAdd(&s_red[128 + rl + 8], pd1);
        }
    }
    __syncthreads();
    if (tid < 128) {
        g_as[row0 + tid] = s_red[tid];
        g_ad[row0 + tid] = s_red[128 + tid];
    }
}

// ---------------- attention weights: w[j]=exp(al-m), rden[d]=1/sum (warp/node) ----------------
__global__ void __launch_bounds__(256) k_att(int l) {
    int d = (blockIdx.x * blockDim.x + threadIdx.x) >> 5;
    int lane = threadIdx.x & 31;
    if (d >= NN) return;
    int beg = g_rowptr[d];
    int end = g_rowptr[d + 1];
    float add = g_ad[d];
    float* ess = g_ess[l];

    float m = -3.0e38f;
    for (int j = beg + lane; j < end; j += 32) {
        float al = g_as[g_srcs[j]] + add + ess[j];
        al = al > 0.f ? al : 0.2f * al;
        m = fmaxf(m, al);
    }
    #pragma unroll
    for (int o = 16; o; o >>= 1) m = fmaxf(m, __shfl_xor_sync(0xffffffffu, m, o));

    float den = 0.f;
    for (int j = beg + lane; j < end; j += 32) {
        float al = g_as[g_srcs[j]] + add + ess[j];
        al = al > 0.f ? al : 0.2f * al;
        float ex = __expf(al - m);
        ess[j] = ex;           // overwrite score with unnormalized weight
        den += ex;
    }
    #pragma unroll
    for (int o = 16; o; o >>= 1) den += __shfl_xor_sync(0xffffffffu, den, o);
    if (lane == 0) g_rden[d] = 1.0f / den;
}

// ---------------- SpMM aggregate + bias + GELU (warp/node, no shfl in hot loop) ----------------
__global__ void __launch_bounds__(256) k_agg(int l, const float* __restrict__ bias_l,
                                             float* __restrict__ outp) {
    int d = (blockIdx.x * blockDim.x + threadIdx.x) >> 5;
    int lane = threadIdx.x & 31;
    if (d >= NN) return;
    float* out = outp ? outp : g_x;

    int beg = g_rowptr[d];
    int end = g_rowptr[d + 1];
    const float* wv = g_ess[l];
    const int* srcs = g_srcs;
    const uint2* h2 = (const uint2*)g_hh;

    float4 acc = make_float4(0.f, 0.f, 0.f, 0.f);

    int j = beg;
    for (; j + 4 <= end; j += 4) {
        int s0 = srcs[j], s1 = srcs[j + 1], s2 = srcs[j + 2], s3 = srcs[j + 3];
        float w0 = wv[j], w1 = wv[j + 1], w2 = wv[j + 2], w3 = wv[j + 3];
        uint2 r0 = h2[(size_t)s0 * 32 + lane];
        uint2 r1 = h2[(size_t)s1 * 32 + lane];
        uint2 r2 = h2[(size_t)s2 * 32 + lane];
        uint2 r3 = h2[(size_t)s3 * 32 + lane];
        float2 a0 = __half22float2(*(__half2*)&r0.x), b0 = __half22float2(*(__half2*)&r0.y);
        float2 a1 = __half22float2(*(__half2*)&r1.x), b1 = __half22float2(*(__half2*)&r1.y);
        float2 a2 = __half22float2(*(__half2*)&r2.x), b2 = __half22float2(*(__half2*)&r2.y);
        float2 a3 = __half22float2(*(__half2*)&r3.x), b3 = __half22float2(*(__half2*)&r3.y);
        acc.x = fmaf(w0, a0.x, fmaf(w1, a1.x, fmaf(w2, a2.x, fmaf(w3, a3.x, acc.x))));
        acc.y = fmaf(w0, a0.y, fmaf(w1, a1.y, fmaf(w2, a2.y, fmaf(w3, a3.y, acc.y))));
        acc.z = fmaf(w0, b0.x, fmaf(w1, b1.x, fmaf(w2, b2.x, fmaf(w3, b3.x, acc.z))));
        acc.w = fmaf(w0, b0.y, fmaf(w1, b1.y, fmaf(w2, b2.y, fmaf(w3, b3.y, acc.w))));
    }
    for (; j < end; j++) {
        int s = srcs[j];
        float w = wv[j];
        uint2 raw = h2[(size_t)s * 32 + lane];
        float2 v0 = __half22float2(*(__half2*)&raw.x);
        float2 v1 = __half22float2(*(__half2*)&raw.y);
        acc.x = fmaf(w, v0.x, acc.x);
        acc.y = fmaf(w, v0.y, acc.y);
        acc.z = fmaf(w, v1.x, acc.z);
        acc.w = fmaf(w, v1.y, acc.w);
    }

    float r = g_rden[d];
    float4 b4 = ((const float4*)bias_l)[lane];
    float4 o4;
    o4.x = gelu_f(fmaf(acc.x, r, b4.x));
    o4.y = gelu_f(fmaf(acc.y, r, b4.y));
    o4.z = gelu_f(fmaf(acc.z, r, b4.z));
    o4.w = gelu_f(fmaf(acc.w, r, b4.w));
    ((float4*)out)[(size_t)d * 32 + lane] = o4;
}

// ---------------- launch ----------------
extern "C" void kernel_launch(void* const* d_in, const int* in_sizes, int n_in,
                              void* d_out, int out_size) {
    const float* x    = (const float*)d_in[0];
    const int*   ei   = (const int*)d_in[1];
    const float* ea   = (const float*)d_in[2];
    const float* Ws   = (const float*)d_in[3];
    const float* a_s  = (const float*)d_in[4];
    const float* a_d  = (const float*)d_in[5];
    const float* We   = (const float*)d_in[6];
    const float* ae   = (const float*)d_in[7];
    const float* bias = (const float*)d_in[8];
    float* out = (float*)d_out;

    const int SMEM_SZ = 4 * 128 * PK * 2;  // 139264 B
    cudaFuncSetAttribute(k_gemm_tc, cudaFuncAttributeMaxDynamicSharedMemorySize, SMEM_SZ);

    k_wsplit<<<449, 256>>>(Ws, We, ae);
    k_hist<<<NE / 256, 256>>>(ei);
    k_bsum<<<256, 256>>>();
    k_bscan<<<1, 256>>>();
    k_rowptr<<<256, 256>>>();
    k_scatter<<<NE / 256, 256>>>(ei, ea);
    k_selfloop<<<NN / 256, 256>>>();

    for (int l = 0; l < 3; l++) {
        const float* xin = (l == 0) ? x : nullptr;
        k_gemm_tc<<<NN / 128, 256, SMEM_SZ>>>(xin, l, a_s + l * DD, a_d + l * DD);
        k_att<<<NN / 8, 256>>>(l);
        float* outl = (l == 2) ? out : nullptr;
        k_agg<<<NN / 8, 256>>>(l, bias + l * DD, outl);
    }
}

// round 10
// speedup vs baseline: 1.0363x; 1.0363x over previous
#include <cuda_runtime.h>
#include <cuda_bf16.h>
#include <cuda_fp16.h>
#include <stdint.h>
#include <math.h>

#define NN 65536
#define NE 524288
#define EX (NE + NN)
#define DD 128
#define PK 136   // padded k-dim (bf16 elems); 272B rows => ldmatrix conflict-free

// ---------------- scratch (device globals: allocation-free) ----------------
__device__ __half g_hh[(size_t)NN * DD];    // 16MB: h in fp16 (agg gather path)
__device__ float g_x[(size_t)NN * DD];      // 32MB: layer activations
__device__ float g_as[NN];
__device__ float g_ad[NN];
__device__ int2  g_epk[3][EX];              // packed (src, score-bits) per layer
__device__ float g_essum[3][NN];
__device__ int   g_rowptr[NN + 1];
__device__ int   g_wslot[NN];
__device__ int   g_cnt[NN];
__device__ int   g_bsum[256];
__device__ float g_ve[3][32];
__device__ __nv_bfloat16 g_wh[3][DD * DD];   // W^T split hi (n-major)
__device__ __nv_bfloat16 g_wl[3][DD * DD];   // W^T split lo (n-major)

__device__ __forceinline__ float gelu_f(float x) {
    return 0.5f * x * (1.0f + erff(x * 0.7071067811865476f));
}

// ---------------- preprocessing ----------------
// blocks 0..191: split W -> bf16 hi/lo (transposed, n-major)
// block 192:     ve[l] = We[l] @ att_edge[l]
// blocks 193..448: zero cnt/essum (+ bsum)
__global__ void k_wsplit(const float* __restrict__ Ws,
                         const float* __restrict__ We, const float* __restrict__ ae) {
    int b = blockIdx.x;
    if (b >= 193) {
        int i = (b - 193) * 256 + threadIdx.x;
        if (i < NN) {
            g_cnt[i] = 0;
            g_essum[0][i] = 0.f; g_essum[1][i] = 0.f; g_essum[2][i] = 0.f;
        }
        if (i < 256) g_bsum[i] = 0;
        return;
    }
    if (b == 192) {
        int t = threadIdx.x;
        if (t < 96) {
            int l = t / 32, k = t % 32;
            const float* w = We + l * 32 * DD + k * DD;
            const float* a = ae + l * DD;
            float s = 0.f;
            #pragma unroll 8
            for (int d = 0; d < DD; d++) s += w[d] * a[d];
            g_ve[l][k] = s;
        }
        return;
    }
    int idx = b * blockDim.x + threadIdx.x;   // 3*128*128
    int l = idx >> 14;
    int rem = idx & 16383;
    int k = rem >> 7, n = rem & 127;
    float v = Ws[idx];
    __nv_bfloat16 h = __float2bfloat16_rn(v);
    float lo = v - __bfloat162float(h);
    g_wh[l][n * DD + k] = h;
    g_wl[l][n * DD + k] = __float2bfloat16_rn(lo);
}

__global__ void k_hist(const int* __restrict__ ei) {
    int e = blockIdx.x * blockDim.x + threadIdx.x;
    if (e < NE) atomicAdd(&g_cnt[ei[NE + e]], 1);
}

// ---- fused one-kernel scan over (cnt[n] + 1): publish block sums, spin, local scan ----
__global__ void __launch_bounds__(256) k_scan256() {
    __shared__ int ws[8], ws2[8], s_base;
    int b = blockIdx.x, t = threadIdx.x;
    int n = b * 256 + t;
    int lane = t & 31, w = t >> 5;
    int v = g_cnt[n] + 1;
    int x = v;
    #pragma unroll
    for (int o = 1; o < 32; o <<= 1) {
        int y = __shfl_up_sync(0xffffffffu, x, o);
        if (lane >= o) x += y;
    }
    if (lane == 31) ws[w] = x;
    __syncthreads();
    if (t < 8) {
        int s = ws[t];
        #pragma unroll
        for (int o = 1; o < 8; o <<= 1) {
            int y = __shfl_up_sync(0xffu, s, o);
            if (t >= o) s += y;
        }
        ws[t] = s;
    }
    __syncthreads();
    int intra = x - v + (w ? ws[w - 1] : 0);   // exclusive within block
    int total = ws[7];                          // block sum (>= 256, never 0)
    if (t == 0) atomicExch(&g_bsum[b], total);  // value-is-flag publish
    // wait for all blocks' sums (all 256 blocks co-resident: no deadlock)
    volatile int* vb = g_bsum;
    int av;
    while ((av = vb[t]) == 0) { }
    int contrib = (t < b) ? av : 0;
    #pragma unroll
    for (int o = 16; o; o >>= 1) contrib += __shfl_xor_sync(0xffffffffu, contrib, o);
    if (lane == 0) ws2[w] = contrib;
    __syncthreads();
    if (t == 0) {
        int s = 0;
        #pragma unroll
        for (int i = 0; i < 8; i++) s += ws2[i];
        s_base = s;
    }
    __syncthreads();
    int excl = s_base + intra;
    g_rowptr[n] = excl;
    g_wslot[n] = excl;
    if (n == NN - 1) g_rowptr[NN] = EX;
}

__global__ void k_scatter(const int* __restrict__ ei, const float* __restrict__ ea) {
    __shared__ float sve[96];
    if (threadIdx.x < 96) sve[threadIdx.x] = ((const float*)g_ve)[threadIdx.x];
    __syncthreads();
    int e = blockIdx.x * blockDim.x + threadIdx.x;
    if (e >= NE) return;
    int s = ei[e];
    int d = ei[NE + e];
    const float4* a4 = (const float4*)(ea + (size_t)e * 32);
    float dot0 = 0.f, dot1 = 0.f, dot2 = 0.f;
    #pragma unroll
    for (int q = 0; q < 8; q++) {
        float4 v = a4[q];
        const float* v0 = sve + 0 * 32 + q * 4;
        const float* v1 = sve + 1 * 32 + q * 4;
        const float* v2 = sve + 2 * 32 + q * 4;
        dot0 += v.x * v0[0] + v.y * v0[1] + v.z * v0[2] + v.w * v0[3];
        dot1 += v.x * v1[0] + v.y * v1[1] + v.z * v1[2] + v.w * v1[3];
        dot2 += v.x * v2[0] + v.y * v2[1] + v.z * v2[2] + v.w * v2[3];
    }
    int p = atomicAdd(&g_wslot[d], 1);
    g_epk[0][p] = make_int2(s, __float_as_int(dot0));
    g_epk[1][p] = make_int2(s, __float_as_int(dot1));
    g_epk[2][p] = make_int2(s, __float_as_int(dot2));
    atomicAdd(&g_essum[0][d], dot0);
    atomicAdd(&g_essum[1][d], dot1);
    atomicAdd(&g_essum[2][d], dot2);
}

__global__ void k_selfloop() {
    int n = blockIdx.x * blockDim.x + threadIdx.x;
    if (n >= NN) return;
    int pos = g_rowptr[n + 1] - 1;
    float cf = fmaxf((float)(g_rowptr[n + 1] - g_rowptr[n] - 1), 1.0f);
    g_epk[0][pos] = make_int2(n, __float_as_int(g_essum[0][n] / cf));
    g_epk[1][pos] = make_int2(n, __float_as_int(g_essum[1][n] / cf));
    g_epk[2][pos] = make_int2(n, __float_as_int(g_essum[2][n] / cf));
}

// ---------------- tensor-core GEMM + fused rowdots, fp16 h output (R6, proven) ----------------
__device__ __forceinline__ void mma16816(float* c, const unsigned* a, const unsigned* b) {
    asm volatile(
        "mma.sync.aligned.m16n8k16.row.col.f32.bf16.bf16.f32 "
        "{%0,%1,%2,%3},{%4,%5,%6,%7},{%8,%9},{%0,%1,%2,%3};\n"
        : "+f"(c[0]), "+f"(c[1]), "+f"(c[2]), "+f"(c[3])
        : "r"(a[0]), "r"(a[1]), "r"(a[2]), "r"(a[3]), "r"(b[0]), "r"(b[1]));
}

__device__ __forceinline__ void ldm_x4(unsigned* r, unsigned addr) {
    asm volatile("ldmatrix.sync.aligned.m8n8.x4.shared.b16 {%0,%1,%2,%3},[%4];"
                 : "=r"(r[0]), "=r"(r[1]), "=r"(r[2]), "=r"(r[3]) : "r"(addr));
}

__device__ __forceinline__ void ldm_x2(unsigned* r, unsigned addr) {
    asm volatile("ldmatrix.sync.aligned.m8n8.x2.shared.b16 {%0,%1},[%2];"
                 : "=r"(r[0]), "=r"(r[1]) : "r"(addr));
}

extern __shared__ char smem_raw[];

__global__ void __launch_bounds__(256) k_gemm_tc(const float* __restrict__ Ain, int l,
                                                 const float* __restrict__ a_s,
                                                 const float* __restrict__ a_d) {
    const float* A = Ain ? Ain : g_x;
    __nv_bfloat16* sAh = (__nv_bfloat16*)smem_raw;
    __nv_bfloat16* sAl = sAh + 128 * PK;
    __nv_bfloat16* sBh = sAl + 128 * PK;
    __nv_bfloat16* sBl = sBh + 128 * PK;

    int tid = threadIdx.x;
    int row0 = blockIdx.x * 128;

    {
        const float4* A4 = (const float4*)(A + (size_t)row0 * DD);
        #pragma unroll
        for (int it = 0; it < 16; it++) {
            int idx = it * 256 + tid;
            int r = idx >> 5;
            int c = (idx & 31) << 2;
            float4 v = A4[idx];
            __nv_bfloat16 h0 = __float2bfloat16_rn(v.x), h1 = __float2bfloat16_rn(v.y);
            __nv_bfloat16 h2 = __float2bfloat16_rn(v.z), h3 = __float2bfloat16_rn(v.w);
            __nv_bfloat162 ha, hb, la, lb;
            ha.x = h0; ha.y = h1; hb.x = h2; hb.y = h3;
            la = __floats2bfloat162_rn(v.x - __bfloat162float(h0), v.y - __bfloat162float(h1));
            lb = __floats2bfloat162_rn(v.z - __bfloat162float(h2), v.w - __bfloat162float(h3));
            unsigned* dh = (unsigned*)(sAh + r * PK + c);
            unsigned* dl = (unsigned*)(sAl + r * PK + c);
            dh[0] = *(unsigned*)&ha; dh[1] = *(unsigned*)&hb;
            dl[0] = *(unsigned*)&la; dl[1] = *(unsigned*)&lb;
        }
    }
    {
        const uint4* wh4 = (const uint4*)g_wh[l];
        const uint4* wl4 = (const uint4*)g_wl[l];
        #pragma unroll
        for (int it = 0; it < 8; it++) {
            int idx = it * 256 + tid;
            int n = idx >> 4;
            int kc = idx & 15;
            ((uint4*)(sBh + n * PK))[kc] = wh4[idx];
            ((uint4*)(sBl + n * PK))[kc] = wl4[idx];
        }
    }
    __syncthreads();

    int wid = tid >> 5, lane = tid & 31;
    int g = lane >> 2, tq = lane & 3;
    int wm = wid >> 2, wn = wid & 3;
    int mbase = wm * 64, nbase = wn * 32;

    unsigned baseAh, baseAl, baseBh, baseBl;
    {
        int aoff = ((mbase + (lane & 15)) * PK + ((lane >> 4) << 3)) * 2;
        baseAh = (unsigned)__cvta_generic_to_shared(sAh) + aoff;
        baseAl = (unsigned)__cvta_generic_to_shared(sAl) + aoff;
        int boff = ((nbase + (lane & 7)) * PK + (((lane >> 3) & 1) << 3)) * 2;
        baseBh = (unsigned)__cvta_generic_to_shared(sBh) + boff;
        baseBl = (unsigned)__cvta_generic_to_shared(sBl) + boff;
    }

    float acc[4][4][4];
    #pragma unroll
    for (int i = 0; i < 4; i++)
        #pragma unroll
        for (int j = 0; j < 4; j++)
            #pragma unroll
            for (int q = 0; q < 4; q++) acc[i][j][q] = 0.f;

    #pragma unroll
    for (int kk = 0; kk < 8; kk++) {
        unsigned kb = kk * 32;
        unsigned Ah[4][4], Al[4][4], Bh[4][2], Bl[4][2];
        #pragma unroll
        for (int i = 0; i < 4; i++) {
            unsigned off = (unsigned)(i * 16 * PK * 2) + kb;
            ldm_x4(Ah[i], baseAh + off);
            ldm_x4(Al[i], baseAl + off);
        }
        #pragma unroll
        for (int j = 0; j < 4; j++) {
            unsigned off = (unsigned)(j * 8 * PK * 2) + kb;
            ldm_x2(Bh[j], baseBh + off);
            ldm_x2(Bl[j], baseBl + off);
        }
        #pragma unroll
        for (int i = 0; i < 4; i++)
            #pragma unroll
            for (int j = 0; j < 4; j++) {
                mma16816(acc[i][j], Ah[i], Bh[j]);
                mma16816(acc[i][j], Al[i], Bh[j]);
                mma16816(acc[i][j], Ah[i], Bl[j]);
            }
    }

    // store h as fp16
    #pragma unroll
    for (int i = 0; i < 4; i++) {
        int r = row0 + mbase + i * 16 + g;
        #pragma unroll
        for (int j = 0; j < 4; j++) {
            int c = nbase + j * 8 + 2 * tq;
            *(__half2*)(g_hh + (size_t)r * DD + c) =
                __float22half2_rn(make_float2(acc[i][j][0], acc[i][j][1]));
            *(__half2*)(g_hh + (size_t)(r + 8) * DD + c) =
                __float22half2_rn(make_float2(acc[i][j][2], acc[i][j][3]));
        }
    }

    // fused rowdots
    float asv[4][2], adv[4][2];
    #pragma unroll
    for (int j = 0; j < 4; j++) {
        int c = nbase + j * 8 + 2 * tq;
        asv[j][0] = a_s[c]; asv[j][1] = a_s[c + 1];
        adv[j][0] = a_d[c]; adv[j][1] = a_d[c + 1];
    }
    __syncthreads();
    float* s_red = (float*)smem_raw;
    if (tid < 128) { s_red[tid] = 0.f; s_red[128 + tid] = 0.f; }
    __syncthreads();
    #pragma unroll
    for (int i = 0; i < 4; i++) {
        float ps0 = 0.f, pd0 = 0.f, ps1 = 0.f, pd1 = 0.f;
        #pragma unroll
        for (int j = 0; j < 4; j++) {
            ps0 += acc[i][j][0] * asv[j][0] + acc[i][j][1] * asv[j][1];
            pd0 += acc[i][j][0] * adv[j][0] + acc[i][j][1] * adv[j][1];
            ps1 += acc[i][j][2] * asv[j][0] + acc[i][j][3] * asv[j][1];
            pd1 += acc[i][j][2] * adv[j][0] + acc[i][j][3] * adv[j][1];
        }
        #pragma unroll
        for (int o = 1; o < 4; o <<= 1) {
            ps0 += __shfl_xor_sync(0xffffffffu, ps0, o);
            pd0 += __shfl_xor_sync(0xffffffffu, pd0, o);
            ps1 += __shfl_xor_sync(0xffffffffu, ps1, o);
            pd1 += __shfl_xor_sync(0xffffffffu, pd1, o);
        }
        if (tq == 0) {
            int rl = mbase + i * 16 + g;
            atomicAdd(&s_red[rl], ps0);
            atomicAdd(&s_red[128 + rl], pd0);
            atomicAdd(&s_red[rl + 8], ps1);
            atomicAdd(&s_red[128 + rl + 8], pd1);
        }
    }
    __syncthreads();
    if (tid < 128) {
        g_as[row0 + tid] = s_red[tid];
        g_ad[row0 + tid] = s_red[128 + tid];
    }
}

// ---------------- single-pass aggregate (direct exp, no max) + bias + GELU ----------------
__global__ void __launch_bounds__(256) k_agg(int l, const float* __restrict__ bias_l,
                                             float* __restrict__ outp) {
    int d = (blockIdx.x * blockDim.x + threadIdx.x) >> 5;
    int lane = threadIdx.x & 31;
    if (d >= NN) return;
    float* out = outp ? outp : g_x;

    int beg = g_rowptr[d];
    int end = g_rowptr[d + 1];
    float add = g_ad[d];
    const int2* ep = g_epk[l];
    const uint2* h2 = (const uint2*)g_hh;

    float den = 0.f;
    float4 acc = make_float4(0.f, 0.f, 0.f, 0.f);

    for (int base = beg; base < end; base += 32) {
        int j = base + lane;
        float ex = 0.f;
        int s = 0;
        if (j < end) {
            int2 e = ep[j];
            s = e.x;
            float al = g_as[s] + add + __int_as_float(e.y);
            al = al > 0.f ? al : 0.2f * al;
            ex = __expf(al);
        }
        den += ex;

        int cnt = end - base;
        if (cnt > 32) cnt = 32;
        for (int t = 0; t < cnt; t++) {
            float ext = __shfl_sync(0xffffffffu, ex, t);
            int st = __shfl_sync(0xffffffffu, s, t);
            uint2 raw = h2[(size_t)st * 32 + lane];
            float2 v0 = __half22float2(*(__half2*)&raw.x);
            float2 v1 = __half22float2(*(__half2*)&raw.y);
            acc.x = fmaf(ext, v0.x, acc.x);
            acc.y = fmaf(ext, v0.y, acc.y);
            acc.z = fmaf(ext, v1.x, acc.z);
            acc.w = fmaf(ext, v1.y, acc.w);
        }
    }
    #pragma unroll
    for (int o = 16; o; o >>= 1) den += __shfl_xor_sync(0xffffffffu, den, o);
    float r = 1.0f / den;

    float4 b4 = ((const float4*)bias_l)[lane];
    float4 o4;
    o4.x = gelu_f(fmaf(acc.x, r, b4.x));
    o4.y = gelu_f(fmaf(acc.y, r, b4.y));
    o4.z = gelu_f(fmaf(acc.z, r, b4.z));
    o4.w = gelu_f(fmaf(acc.w, r, b4.w));
    ((float4*)out)[(size_t)d * 32 + lane] = o4;
}

// ---------------- launch ----------------
extern "C" void kernel_launch(void* const* d_in, const int* in_sizes, int n_in,
                              void* d_out, int out_size) {
    const float* x    = (const float*)d_in[0];
    const int*   ei   = (const int*)d_in[1];
    const float* ea   = (const float*)d_in[2];
    const float* Ws   = (const float*)d_in[3];
    const float* a_s  = (const float*)d_in[4];
    const float* a_d  = (const float*)d_in[5];
    const float* We   = (const float*)d_in[6];
    const float* ae   = (const float*)d_in[7];
    const float* bias = (const float*)d_in[8];
    float* out = (float*)d_out;

    const int SMEM_SZ = 4 * 128 * PK * 2;  // 139264 B
    cudaFuncSetAttribute(k_gemm_tc, cudaFuncAttributeMaxDynamicSharedMemorySize, SMEM_SZ);

    k_wsplit<<<449, 256>>>(Ws, We, ae);
    k_hist<<<NE / 256, 256>>>(ei);
    k_scan256<<<256, 256>>>();
    k_scatter<<<NE / 256, 256>>>(ei, ea);
    k_selfloop<<<NN / 256, 256>>>();

    for (int l = 0; l < 3; l++) {
        const float* xin = (l == 0) ? x : nullptr;
        k_gemm_tc<<<NN / 128, 256, SMEM_SZ>>>(xin, l, a_s + l * DD, a_d + l * DD);
        float* outl = (l == 2) ? out : nullptr;
        k_agg<<<NN / 8, 256>>>(l, bias + l * DD, outl);
    }
}

// round 11
// speedup vs baseline: 1.0637x; 1.0264x over previous
#include <cuda_runtime.h>
#include <cuda_bf16.h>
#include <cuda_fp16.h>
#include <stdint.h>
#include <math.h>

#define NN 65536
#define NE 524288
#define EX (NE + NN)
#define DD 128
#define PK 136   // padded k-dim (bf16 elems); 272B rows => ldmatrix conflict-free

// ---------------- scratch (device globals: allocation-free) ----------------
__device__ __half g_hh[(size_t)NN * DD];    // 16MB: h in fp16 (agg gather path)
__device__ float g_x[(size_t)NN * DD];      // 32MB: layer activations
__device__ float g_as[NN];
__device__ float g_ad[NN];
__device__ int4  g_epk4[EX];                // packed (src, s0, s1, s2) per CSR slot
__device__ int   g_rowptr[NN + 1];
__device__ int   g_wslot[NN];
__device__ int   g_cnt[NN];
__device__ int   g_bsum[256];
__device__ float g_ve[3][32];
__device__ __nv_bfloat16 g_wh[3][DD * DD];   // W^T split hi (n-major)
__device__ __nv_bfloat16 g_wl[3][DD * DD];   // W^T split lo (n-major)

__device__ __forceinline__ float gelu_f(float x) {
    return 0.5f * x * (1.0f + erff(x * 0.7071067811865476f));
}

// ---------------- preprocessing ----------------
// blocks 0..191: split W -> bf16 hi/lo (transposed, n-major)
// block 192:     ve[l] = We[l] @ att_edge[l]
// blocks 193..448: zero cnt (+ bsum)
__global__ void k_wsplit(const float* __restrict__ Ws,
                         const float* __restrict__ We, const float* __restrict__ ae) {
    int b = blockIdx.x;
    if (b >= 193) {
        int i = (b - 193) * 256 + threadIdx.x;
        if (i < NN) g_cnt[i] = 0;
        if (i < 256) g_bsum[i] = 0;
        return;
    }
    if (b == 192) {
        int t = threadIdx.x;
        if (t < 96) {
            int l = t / 32, k = t % 32;
            const float* w = We + l * 32 * DD + k * DD;
            const float* a = ae + l * DD;
            float s = 0.f;
            #pragma unroll 8
            for (int d = 0; d < DD; d++) s += w[d] * a[d];
            g_ve[l][k] = s;
        }
        return;
    }
    int idx = b * blockDim.x + threadIdx.x;   // 3*128*128
    int l = idx >> 14;
    int rem = idx & 16383;
    int k = rem >> 7, n = rem & 127;
    float v = Ws[idx];
    __nv_bfloat16 h = __float2bfloat16_rn(v);
    float lo = v - __bfloat162float(h);
    g_wh[l][n * DD + k] = h;
    g_wl[l][n * DD + k] = __float2bfloat16_rn(lo);
}

__global__ void k_hist(const int* __restrict__ ei) {
    int e = blockIdx.x * blockDim.x + threadIdx.x;
    if (e < NE) atomicAdd(&g_cnt[ei[NE + e]], 1);
}

// ---- fused one-kernel scan over (cnt[n] + 1): publish block sums, spin, local scan ----
__global__ void __launch_bounds__(256) k_scan256() {
    __shared__ int ws[8], ws2[8], s_base;
    int b = blockIdx.x, t = threadIdx.x;
    int n = b * 256 + t;
    int lane = t & 31, w = t >> 5;
    int v = g_cnt[n] + 1;
    int x = v;
    #pragma unroll
    for (int o = 1; o < 32; o <<= 1) {
        int y = __shfl_up_sync(0xffffffffu, x, o);
        if (lane >= o) x += y;
    }
    if (lane == 31) ws[w] = x;
    __syncthreads();
    if (t < 8) {
        int s = ws[t];
        #pragma unroll
        for (int o = 1; o < 8; o <<= 1) {
            int y = __shfl_up_sync(0xffu, s, o);
            if (t >= o) s += y;
        }
        ws[t] = s;
    }
    __syncthreads();
    int intra = x - v + (w ? ws[w - 1] : 0);   // exclusive within block
    int total = ws[7];                          // block sum (>= 256, never 0)
    if (t == 0) atomicExch(&g_bsum[b], total);  // value-is-flag publish
    volatile int* vb = g_bsum;
    int av;
    while ((av = vb[t]) == 0) { }
    int contrib = (t < b) ? av : 0;
    #pragma unroll
    for (int o = 16; o; o >>= 1) contrib += __shfl_xor_sync(0xffffffffu, contrib, o);
    if (lane == 0) ws2[w] = contrib;
    __syncthreads();
    if (t == 0) {
        int s = 0;
        #pragma unroll
        for (int i = 0; i < 8; i++) s += ws2[i];
        s_base = s;
    }
    __syncthreads();
    int excl = s_base + intra;
    g_rowptr[n] = excl;
    g_wslot[n] = excl;
    if (n == NN - 1) g_rowptr[NN] = EX;
}

__global__ void k_scatter(const int* __restrict__ ei, const float* __restrict__ ea) {
    __shared__ float sve[96];
    if (threadIdx.x < 96) sve[threadIdx.x] = ((const float*)g_ve)[threadIdx.x];
    __syncthreads();
    int e = blockIdx.x * blockDim.x + threadIdx.x;
    if (e >= NE) return;
    int s = ei[e];
    int d = ei[NE + e];
    const float4* a4 = (const float4*)(ea + (size_t)e * 32);
    float dot0 = 0.f, dot1 = 0.f, dot2 = 0.f;
    #pragma unroll
    for (int q = 0; q < 8; q++) {
        float4 v = a4[q];
        const float* v0 = sve + 0 * 32 + q * 4;
        const float* v1 = sve + 1 * 32 + q * 4;
        const float* v2 = sve + 2 * 32 + q * 4;
        dot0 += v.x * v0[0] + v.y * v0[1] + v.z * v0[2] + v.w * v0[3];
        dot1 += v.x * v1[0] + v.y * v1[1] + v.z * v1[2] + v.w * v1[3];
        dot2 += v.x * v2[0] + v.y * v2[1] + v.z * v2[2] + v.w * v2[3];
    }
    int p = atomicAdd(&g_wslot[d], 1);
    g_epk4[p] = make_int4(s, __float_as_int(dot0), __float_as_int(dot1), __float_as_int(dot2));
}

// warp per node: sum scores over own CSR row (coalesced), write self-loop slot
__global__ void __launch_bounds__(256) k_selfloop() {
    int n = (blockIdx.x * blockDim.x + threadIdx.x) >> 5;
    int lane = threadIdx.x & 31;
    if (n >= NN) return;
    int beg = g_rowptr[n];
    int end1 = g_rowptr[n + 1] - 1;     // edges occupy [beg, end1); self-loop at end1
    float s0 = 0.f, s1 = 0.f, s2 = 0.f;
    for (int j = beg + lane; j < end1; j += 32) {
        int4 e = g_epk4[j];
        s0 += __int_as_float(e.y);
        s1 += __int_as_float(e.z);
        s2 += __int_as_float(e.w);
    }
    #pragma unroll
    for (int o = 16; o; o >>= 1) {
        s0 += __shfl_xor_sync(0xffffffffu, s0, o);
        s1 += __shfl_xor_sync(0xffffffffu, s1, o);
        s2 += __shfl_xor_sync(0xffffffffu, s2, o);
    }
    if (lane == 0) {
        float cf = fmaxf((float)(end1 - beg), 1.0f);
        g_epk4[end1] = make_int4(n, __float_as_int(s0 / cf),
                                 __float_as_int(s1 / cf), __float_as_int(s2 / cf));
    }
}

// ---------------- tensor-core GEMM + fused rowdots, fp16 h output (R6, proven) ----------------
__device__ __forceinline__ void mma16816(float* c, const unsigned* a, const unsigned* b) {
    asm volatile(
        "mma.sync.aligned.m16n8k16.row.col.f32.bf16.bf16.f32 "
        "{%0,%1,%2,%3},{%4,%5,%6,%7},{%8,%9},{%0,%1,%2,%3};\n"
        : "+f"(c[0]), "+f"(c[1]), "+f"(c[2]), "+f"(c[3])
        : "r"(a[0]), "r"(a[1]), "r"(a[2]), "r"(a[3]), "r"(b[0]), "r"(b[1]));
}

__device__ __forceinline__ void ldm_x4(unsigned* r, unsigned addr) {
    asm volatile("ldmatrix.sync.aligned.m8n8.x4.shared.b16 {%0,%1,%2,%3},[%4];"
                 : "=r"(r[0]), "=r"(r[1]), "=r"(r[2]), "=r"(r[3]) : "r"(addr));
}

__device__ __forceinline__ void ldm_x2(unsigned* r, unsigned addr) {
    asm volatile("ldmatrix.sync.aligned.m8n8.x2.shared.b16 {%0,%1},[%2];"
                 : "=r"(r[0]), "=r"(r[1]) : "r"(addr));
}

extern __shared__ char smem_raw[];

__global__ void __launch_bounds__(256) k_gemm_tc(const float* __restrict__ Ain, int l,
                                                 const float* __restrict__ a_s,
                                                 const float* __restrict__ a_d) {
    const float* A = Ain ? Ain : g_x;
    __nv_bfloat16* sAh = (__nv_bfloat16*)smem_raw;
    __nv_bfloat16* sAl = sAh + 128 * PK;
    __nv_bfloat16* sBh = sAl + 128 * PK;
    __nv_bfloat16* sBl = sBh + 128 * PK;

    int tid = threadIdx.x;
    int row0 = blockIdx.x * 128;

    {
        const float4* A4 = (const float4*)(A + (size_t)row0 * DD);
        #pragma unroll
        for (int it = 0; it < 16; it++) {
            int idx = it * 256 + tid;
            int r = idx >> 5;
            int c = (idx & 31) << 2;
            float4 v = A4[idx];
            __nv_bfloat16 h0 = __float2bfloat16_rn(v.x), h1 = __float2bfloat16_rn(v.y);
            __nv_bfloat16 h2 = __float2bfloat16_rn(v.z), h3 = __float2bfloat16_rn(v.w);
            __nv_bfloat162 ha, hb, la, lb;
            ha.x = h0; ha.y = h1; hb.x = h2; hb.y = h3;
            la = __floats2bfloat162_rn(v.x - __bfloat162float(h0), v.y - __bfloat162float(h1));
            lb = __floats2bfloat162_rn(v.z - __bfloat162float(h2), v.w - __bfloat162float(h3));
            unsigned* dh = (unsigned*)(sAh + r * PK + c);
            unsigned* dl = (unsigned*)(sAl + r * PK + c);
            dh[0] = *(unsigned*)&ha; dh[1] = *(unsigned*)&hb;
            dl[0] = *(unsigned*)&la; dl[1] = *(unsigned*)&lb;
        }
    }
    {
        const uint4* wh4 = (const uint4*)g_wh[l];
        const uint4* wl4 = (const uint4*)g_wl[l];
        #pragma unroll
        for (int it = 0; it < 8; it++) {
            int idx = it * 256 + tid;
            int n = idx >> 4;
            int kc = idx & 15;
            ((uint4*)(sBh + n * PK))[kc] = wh4[idx];
            ((uint4*)(sBl + n * PK))[kc] = wl4[idx];
        }
    }
    __syncthreads();

    int wid = tid >> 5, lane = tid & 31;
    int g = lane >> 2, tq = lane & 3;
    int wm = wid >> 2, wn = wid & 3;
    int mbase = wm * 64, nbase = wn * 32;

    unsigned baseAh, baseAl, baseBh, baseBl;
    {
        int aoff = ((mbase + (lane & 15)) * PK + ((lane >> 4) << 3)) * 2;
        baseAh = (unsigned)__cvta_generic_to_shared(sAh) + aoff;
        baseAl = (unsigned)__cvta_generic_to_shared(sAl) + aoff;
        int boff = ((nbase + (lane & 7)) * PK + (((lane >> 3) & 1) << 3)) * 2;
        baseBh = (unsigned)__cvta_generic_to_shared(sBh) + boff;
        baseBl = (unsigned)__cvta_generic_to_shared(sBl) + boff;
    }

    float acc[4][4][4];
    #pragma unroll
    for (int i = 0; i < 4; i++)
        #pragma unroll
        for (int j = 0; j < 4; j++)
            #pragma unroll
            for (int q = 0; q < 4; q++) acc[i][j][q] = 0.f;

    #pragma unroll
    for (int kk = 0; kk < 8; kk++) {
        unsigned kb = kk * 32;
        unsigned Ah[4][4], Al[4][4], Bh[4][2], Bl[4][2];
        #pragma unroll
        for (int i = 0; i < 4; i++) {
            unsigned off = (unsigned)(i * 16 * PK * 2) + kb;
            ldm_x4(Ah[i], baseAh + off);
            ldm_x4(Al[i], baseAl + off);
        }
        #pragma unroll
        for (int j = 0; j < 4; j++) {
            unsigned off = (unsigned)(j * 8 * PK * 2) + kb;
            ldm_x2(Bh[j], baseBh + off);
            ldm_x2(Bl[j], baseBl + off);
        }
        #pragma unroll
        for (int i = 0; i < 4; i++)
            #pragma unroll
            for (int j = 0; j < 4; j++) {
                mma16816(acc[i][j], Ah[i], Bh[j]);
                mma16816(acc[i][j], Al[i], Bh[j]);
                mma16816(acc[i][j], Ah[i], Bl[j]);
            }
    }

    // store h as fp16
    #pragma unroll
    for (int i = 0; i < 4; i++) {
        int r = row0 + mbase + i * 16 + g;
        #pragma unroll
        for (int j = 0; j < 4; j++) {
            int c = nbase + j * 8 + 2 * tq;
            *(__half2*)(g_hh + (size_t)r * DD + c) =
                __float22half2_rn(make_float2(acc[i][j][0], acc[i][j][1]));
            *(__half2*)(g_hh + (size_t)(r + 8) * DD + c) =
                __float22half2_rn(make_float2(acc[i][j][2], acc[i][j][3]));
        }
    }

    // fused rowdots
    float asv[4][2], adv[4][2];
    #pragma unroll
    for (int j = 0; j < 4; j++) {
        int c = nbase + j * 8 + 2 * tq;
        asv[j][0] = a_s[c]; asv[j][1] = a_s[c + 1];
        adv[j][0] = a_d[c]; adv[j][1] = a_d[c + 1];
    }
    __syncthreads();
    float* s_red = (float*)smem_raw;
    if (tid < 128) { s_red[tid] = 0.f; s_red[128 + tid] = 0.f; }
    __syncthreads();
    #pragma unroll
    for (int i = 0; i < 4; i++) {
        float ps0 = 0.f, pd0 = 0.f, ps1 = 0.f, pd1 = 0.f;
        #pragma unroll
        for (int j = 0; j < 4; j++) {
            ps0 += acc[i][j][0] * asv[j][0] + acc[i][j][1] * asv[j][1];
            pd0 += acc[i][j][0] * adv[j][0] + acc[i][j][1] * adv[j][1];
            ps1 += acc[i][j][2] * asv[j][0] + acc[i][j][3] * asv[j][1];
            pd1 += acc[i][j][2] * adv[j][0] + acc[i][j][3] * adv[j][1];
        }
        #pragma unroll
        for (int o = 1; o < 4; o <<= 1) {
            ps0 += __shfl_xor_sync(0xffffffffu, ps0, o);
            pd0 += __shfl_xor_sync(0xffffffffu, pd0, o);
            ps1 += __shfl_xor_sync(0xffffffffu, ps1, o);
            pd1 += __shfl_xor_sync(0xffffffffu, pd1, o);
        }
        if (tq == 0) {
            int rl = mbase + i * 16 + g;
            atomicAdd(&s_red[rl], ps0);
            atomicAdd(&s_red[128 + rl], pd0);
            atomicAdd(&s_red[rl + 8], ps1);
            atomicAdd(&s_red[128 + rl + 8], pd1);
        }
    }
    __syncthreads();
    if (tid < 128) {
        g_as[row0 + tid] = s_red[tid];
        g_ad[row0 + tid] = s_red[128 + tid];
    }
}

// ---------------- single-pass aggregate (direct exp, no max) + bias + GELU ----------------
__global__ void __launch_bounds__(256) k_agg(int l, const float* __restrict__ bias_l,
                                             float* __restrict__ outp) {
    int d = (blockIdx.x * blockDim.x + threadIdx.x) >> 5;
    int lane = threadIdx.x & 31;
    if (d >= NN) return;
    float* out = outp ? outp : g_x;

    int beg = g_rowptr[d];
    int end = g_rowptr[d + 1];
    float add = g_ad[d];
    const int4* ep = g_epk4;
    const uint2* h2 = (const uint2*)g_hh;

    float den = 0.f;
    float4 acc = make_float4(0.f, 0.f, 0.f, 0.f);

    for (int base = beg; base < end; base += 32) {
        int j = base + lane;
        float ex = 0.f;
        int s = 0;
        if (j < end) {
            int4 e = ep[j];
            s = e.x;
            int sb = (l == 0) ? e.y : (l == 1) ? e.z : e.w;
            float al = g_as[s] + add + __int_as_float(sb);
            al = al > 0.f ? al : 0.2f * al;
            ex = __expf(al);
        }
        den += ex;

        int cnt = end - base;
        if (cnt > 32) cnt = 32;
        for (int t = 0; t < cnt; t++) {
            float ext = __shfl_sync(0xffffffffu, ex, t);
            int st = __shfl_sync(0xffffffffu, s, t);
            uint2 raw = h2[(size_t)st * 32 + lane];
            float2 v0 = __half22float2(*(__half2*)&raw.x);
            float2 v1 = __half22float2(*(__half2*)&raw.y);
            acc.x = fmaf(ext, v0.x, acc.x);
            acc.y = fmaf(ext, v0.y, acc.y);
            acc.z = fmaf(ext, v1.x, acc.z);
            acc.w = fmaf(ext, v1.y, acc.w);
        }
    }
    #pragma unroll
    for (int o = 16; o; o >>= 1) den += __shfl_xor_sync(0xffffffffu, den, o);
    float r = 1.0f / den;

    float4 b4 = ((const float4*)bias_l)[lane];
    float4 o4;
    o4.x = gelu_f(fmaf(acc.x, r, b4.x));
    o4.y = gelu_f(fmaf(acc.y, r, b4.y));
    o4.z = gelu_f(fmaf(acc.z, r, b4.z));
    o4.w = gelu_f(fmaf(acc.w, r, b4.w));
    ((float4*)out)[(size_t)d * 32 + lane] = o4;
}

// ---------------- launch ----------------
extern "C" void kernel_launch(void* const* d_in, const int* in_sizes, int n_in,
                              void* d_out, int out_size) {
    const float* x    = (const float*)d_in[0];
    const int*   ei   = (const int*)d_in[1];
    const float* ea   = (const float*)d_in[2];
    const float* Ws   = (const float*)d_in[3];
    const float* a_s  = (const float*)d_in[4];
    const float* a_d  = (const float*)d_in[5];
    const float* We   = (const float*)d_in[6];
    const float* ae   = (const float*)d_in[7];
    const float* bias = (const float*)d_in[8];
    float* out = (float*)d_out;

    const int SMEM_SZ = 4 * 128 * PK * 2;  // 139264 B
    cudaFuncSetAttribute(k_gemm_tc, cudaFuncAttributeMaxDynamicSharedMemorySize, SMEM_SZ);

    k_wsplit<<<449, 256>>>(Ws, We, ae);
    k_hist<<<NE / 256, 256>>>(ei);
    k_scan256<<<256, 256>>>();
    k_scatter<<<NE / 256, 256>>>(ei, ea);
    k_selfloop<<<NN / 8, 256>>>();

    for (int l = 0; l < 3; l++) {
        const float* xin = (l == 0) ? x : nullptr;
        k_gemm_tc<<<NN / 128, 256, SMEM_SZ>>>(xin, l, a_s + l * DD, a_d + l * DD);
        float* outl = (l == 2) ? out : nullptr;
        k_agg<<<NN / 8, 256>>>(l, bias + l * DD, outl);
    }
}

// round 12
// speedup vs baseline: 1.0975x; 1.0317x over previous
#include <cuda_runtime.h>
#include <cuda_bf16.h>
#include <cuda_fp16.h>
#include <stdint.h>
#include <math.h>

#define NN 65536
#define NE 524288
#define EX (NE + NN)
#define DD 128
#define PK 136   // padded k-dim (bf16 elems); 272B rows => ldmatrix conflict-free

// ---------------- scratch (device globals: allocation-free) ----------------
__device__ __half g_hh[(size_t)NN * DD];    // 16MB: h in fp16 (agg gather path)
__device__ float g_x[(size_t)NN * DD];      // 32MB: layer activations
__device__ float g_as[NN];
__device__ float g_ad[NN];
__device__ int4  g_epk4[EX];                // packed (src, s0, s1, s2) per CSR slot
__device__ int   g_rowptr[NN + 1];
__device__ int   g_wslot[NN];
__device__ int   g_cnt[NN];
__device__ int   g_bsum[256];
__device__ float g_ve[3][32];
__device__ __nv_bfloat16 g_wh[3][DD * DD];   // W^T split hi (n-major)
__device__ __nv_bfloat16 g_wl[3][DD * DD];   // W^T split lo (n-major)

__device__ __forceinline__ float gelu_f(float x) {
    return 0.5f * x * (1.0f + erff(x * 0.7071067811865476f));
}

// ---------------- preprocessing ----------------
// blocks 0..191: split W -> bf16 hi/lo (transposed, n-major)
// block 192:     ve[l] = We[l] @ att_edge[l]
// blocks 193..448: zero cnt (+ bsum)
__global__ void k_wsplit(const float* __restrict__ Ws,
                         const float* __restrict__ We, const float* __restrict__ ae) {
    int b = blockIdx.x;
    if (b >= 193) {
        int i = (b - 193) * 256 + threadIdx.x;
        if (i < NN) g_cnt[i] = 0;
        if (i < 256) g_bsum[i] = 0;
        return;
    }
    if (b == 192) {
        int t = threadIdx.x;
        if (t < 96) {
            int l = t / 32, k = t % 32;
            const float* w = We + l * 32 * DD + k * DD;
            const float* a = ae + l * DD;
            float s = 0.f;
            #pragma unroll 8
            for (int d = 0; d < DD; d++) s += w[d] * a[d];
            g_ve[l][k] = s;
        }
        return;
    }
    int idx = b * blockDim.x + threadIdx.x;   // 3*128*128
    int l = idx >> 14;
    int rem = idx & 16383;
    int k = rem >> 7, n = rem & 127;
    float v = Ws[idx];
    __nv_bfloat16 h = __float2bfloat16_rn(v);
    float lo = v - __bfloat162float(h);
    g_wh[l][n * DD + k] = h;
    g_wl[l][n * DD + k] = __float2bfloat16_rn(lo);
}

__global__ void k_hist(const int* __restrict__ ei) {
    int e = blockIdx.x * blockDim.x + threadIdx.x;
    if (e < NE) atomicAdd(&g_cnt[ei[NE + e]], 1);
}

// ---- fused one-kernel scan over (cnt[n] + 1): publish block sums, spin, local scan ----
__global__ void __launch_bounds__(256) k_scan256() {
    __shared__ int ws[8], ws2[8], s_base;
    int b = blockIdx.x, t = threadIdx.x;
    int n = b * 256 + t;
    int lane = t & 31, w = t >> 5;
    int v = g_cnt[n] + 1;
    int x = v;
    #pragma unroll
    for (int o = 1; o < 32; o <<= 1) {
        int y = __shfl_up_sync(0xffffffffu, x, o);
        if (lane >= o) x += y;
    }
    if (lane == 31) ws[w] = x;
    __syncthreads();
    if (t < 8) {
        int s = ws[t];
        #pragma unroll
        for (int o = 1; o < 8; o <<= 1) {
            int y = __shfl_up_sync(0xffu, s, o);
            if (t >= o) s += y;
        }
        ws[t] = s;
    }
    __syncthreads();
    int intra = x - v + (w ? ws[w - 1] : 0);
    int total = ws[7];
    if (t == 0) atomicExch(&g_bsum[b], total);
    volatile int* vb = g_bsum;
    int av;
    while ((av = vb[t]) == 0) { }
    int contrib = (t < b) ? av : 0;
    #pragma unroll
    for (int o = 16; o; o >>= 1) contrib += __shfl_xor_sync(0xffffffffu, contrib, o);
    if (lane == 0) ws2[w] = contrib;
    __syncthreads();
    if (t == 0) {
        int s = 0;
        #pragma unroll
        for (int i = 0; i < 8; i++) s += ws2[i];
        s_base = s;
    }
    __syncthreads();
    int excl = s_base + intra;
    g_rowptr[n] = excl;
    g_wslot[n] = excl;
    if (n == NN - 1) g_rowptr[NN] = EX;
}

// warp handles 32 edges: coalesced 4KB attr load -> swizzled smem -> per-lane dots
__global__ void __launch_bounds__(256) k_scatter(const int* __restrict__ ei,
                                                 const float* __restrict__ ea) {
    __shared__ float sve[96];
    __shared__ __align__(16) char sbuf[8][4096];
    int tid = threadIdx.x;
    if (tid < 96) sve[tid] = ((const float*)g_ve)[tid];
    __syncthreads();
    int wid = tid >> 5, lane = tid & 31;
    int e = blockIdx.x * 256 + tid;                 // this lane's edge
    int ebase = blockIdx.x * 256 + wid * 32;        // warp's first edge

    // coalesced load: 4KB contiguous, swizzled store (SW128 pattern)
    const float4* src = (const float4*)(ea + (size_t)ebase * 32);
    #pragma unroll
    for (int q = 0; q < 8; q++) {
        int idx = q * 32 + lane;
        uint32_t boff = (uint32_t)idx * 16u;
        uint32_t sw = boff ^ ((boff >> 3) & 0x70u);
        *(float4*)(sbuf[wid] + sw) = src[idx];
    }
    __syncwarp();

    // per-lane dots over own row (conflict-free via swizzle)
    float dot0 = 0.f, dot1 = 0.f, dot2 = 0.f;
    #pragma unroll
    for (int q = 0; q < 8; q++) {
        uint32_t boff = (uint32_t)lane * 128u + (uint32_t)q * 16u;
        uint32_t sw = boff ^ ((boff >> 3) & 0x70u);
        float4 v = *(const float4*)(sbuf[wid] + sw);
        const float* v0 = sve + 0 * 32 + q * 4;
        const float* v1 = sve + 1 * 32 + q * 4;
        const float* v2 = sve + 2 * 32 + q * 4;
        dot0 += v.x * v0[0] + v.y * v0[1] + v.z * v0[2] + v.w * v0[3];
        dot1 += v.x * v1[0] + v.y * v1[1] + v.z * v1[2] + v.w * v1[3];
        dot2 += v.x * v2[0] + v.y * v2[1] + v.z * v2[2] + v.w * v2[3];
    }

    int s = ei[e];
    int d = ei[NE + e];
    int p = atomicAdd(&g_wslot[d], 1);
    g_epk4[p] = make_int4(s, __float_as_int(dot0), __float_as_int(dot1), __float_as_int(dot2));
}

// warp per node: sum scores over own CSR row (coalesced), write self-loop slot
__global__ void __launch_bounds__(256) k_selfloop() {
    int n = (blockIdx.x * blockDim.x + threadIdx.x) >> 5;
    int lane = threadIdx.x & 31;
    if (n >= NN) return;
    int beg = g_rowptr[n];
    int end1 = g_rowptr[n + 1] - 1;
    float s0 = 0.f, s1 = 0.f, s2 = 0.f;
    for (int j = beg + lane; j < end1; j += 32) {
        int4 e = g_epk4[j];
        s0 += __int_as_float(e.y);
        s1 += __int_as_float(e.z);
        s2 += __int_as_float(e.w);
    }
    #pragma unroll
    for (int o = 16; o; o >>= 1) {
        s0 += __shfl_xor_sync(0xffffffffu, s0, o);
        s1 += __shfl_xor_sync(0xffffffffu, s1, o);
        s2 += __shfl_xor_sync(0xffffffffu, s2, o);
    }
    if (lane == 0) {
        float cf = fmaxf((float)(end1 - beg), 1.0f);
        g_epk4[end1] = make_int4(n, __float_as_int(s0 / cf),
                                 __float_as_int(s1 / cf), __float_as_int(s2 / cf));
    }
}

// ---------------- tensor-core GEMM + fused rowdots, fp16 h output (R6, proven) ----------------
__device__ __forceinline__ void mma16816(float* c, const unsigned* a, const unsigned* b) {
    asm volatile(
        "mma.sync.aligned.m16n8k16.row.col.f32.bf16.bf16.f32 "
        "{%0,%1,%2,%3},{%4,%5,%6,%7},{%8,%9},{%0,%1,%2,%3};\n"
        : "+f"(c[0]), "+f"(c[1]), "+f"(c[2]), "+f"(c[3])
        : "r"(a[0]), "r"(a[1]), "r"(a[2]), "r"(a[3]), "r"(b[0]), "r"(b[1]));
}

__device__ __forceinline__ void ldm_x4(unsigned* r, unsigned addr) {
    asm volatile("ldmatrix.sync.aligned.m8n8.x4.shared.b16 {%0,%1,%2,%3},[%4];"
                 : "=r"(r[0]), "=r"(r[1]), "=r"(r[2]), "=r"(r[3]) : "r"(addr));
}

__device__ __forceinline__ void ldm_x2(unsigned* r, unsigned addr) {
    asm volatile("ldmatrix.sync.aligned.m8n8.x2.shared.b16 {%0,%1},[%2];"
                 : "=r"(r[0]), "=r"(r[1]) : "r"(addr));
}

extern __shared__ char smem_raw[];

__global__ void __launch_bounds__(256) k_gemm_tc(const float* __restrict__ Ain, int l,
                                                 const float* __restrict__ a_s,
                                                 const float* __restrict__ a_d) {
    const float* A = Ain ? Ain : g_x;
    __nv_bfloat16* sAh = (__nv_bfloat16*)smem_raw;
    __nv_bfloat16* sAl = sAh + 128 * PK;
    __nv_bfloat16* sBh = sAl + 128 * PK;
    __nv_bfloat16* sBl = sBh + 128 * PK;

    int tid = threadIdx.x;
    int row0 = blockIdx.x * 128;

    {
        const float4* A4 = (const float4*)(A + (size_t)row0 * DD);
        #pragma unroll
        for (int it = 0; it < 16; it++) {
            int idx = it * 256 + tid;
            int r = idx >> 5;
            int c = (idx & 31) << 2;
            float4 v = A4[idx];
            __nv_bfloat16 h0 = __float2bfloat16_rn(v.x), h1 = __float2bfloat16_rn(v.y);
            __nv_bfloat16 h2 = __float2bfloat16_rn(v.z), h3 = __float2bfloat16_rn(v.w);
            __nv_bfloat162 ha, hb, la, lb;
            ha.x = h0; ha.y = h1; hb.x = h2; hb.y = h3;
            la = __floats2bfloat162_rn(v.x - __bfloat162float(h0), v.y - __bfloat162float(h1));
            lb = __floats2bfloat162_rn(v.z - __bfloat162float(h2), v.w - __bfloat162float(h3));
            unsigned* dh = (unsigned*)(sAh + r * PK + c);
            unsigned* dl = (unsigned*)(sAl + r * PK + c);
            dh[0] = *(unsigned*)&ha; dh[1] = *(unsigned*)&hb;
            dl[0] = *(unsigned*)&la; dl[1] = *(unsigned*)&lb;
        }
    }
    {
        const uint4* wh4 = (const uint4*)g_wh[l];
        const uint4* wl4 = (const uint4*)g_wl[l];
        #pragma unroll
        for (int it = 0; it < 8; it++) {
            int idx = it * 256 + tid;
            int n = idx >> 4;
            int kc = idx & 15;
            ((uint4*)(sBh + n * PK))[kc] = wh4[idx];
            ((uint4*)(sBl + n * PK))[kc] = wl4[idx];
        }
    }
    __syncthreads();

    int wid = tid >> 5, lane = tid & 31;
    int g = lane >> 2, tq = lane & 3;
    int wm = wid >> 2, wn = wid & 3;
    int mbase = wm * 64, nbase = wn * 32;

    unsigned baseAh, baseAl, baseBh, baseBl;
    {
        int aoff = ((mbase + (lane & 15)) * PK + ((lane >> 4) << 3)) * 2;
        baseAh = (unsigned)__cvta_generic_to_shared(sAh) + aoff;
        baseAl = (unsigned)__cvta_generic_to_shared(sAl) + aoff;
        int boff = ((nbase + (lane & 7)) * PK + (((lane >> 3) & 1) << 3)) * 2;
        baseBh = (unsigned)__cvta_generic_to_shared(sBh) + boff;
        baseBl = (unsigned)__cvta_generic_to_shared(sBl) + boff;
    }

    float acc[4][4][4];
    #pragma unroll
    for (int i = 0; i < 4; i++)
        #pragma unroll
        for (int j = 0; j < 4; j++)
            #pragma unroll
            for (int q = 0; q < 4; q++) acc[i][j][q] = 0.f;

    #pragma unroll
    for (int kk = 0; kk < 8; kk++) {
        unsigned kb = kk * 32;
        unsigned Ah[4][4], Al[4][4], Bh[4][2], Bl[4][2];
        #pragma unroll
        for (int i = 0; i < 4; i++) {
            unsigned off = (unsigned)(i * 16 * PK * 2) + kb;
            ldm_x4(Ah[i], baseAh + off);
            ldm_x4(Al[i], baseAl + off);
        }
        #pragma unroll
        for (int j = 0; j < 4; j++) {
            unsigned off = (unsigned)(j * 8 * PK * 2) + kb;
            ldm_x2(Bh[j], baseBh + off);
            ldm_x2(Bl[j], baseBl + off);
        }
        #pragma unroll
        for (int i = 0; i < 4; i++)
            #pragma unroll
            for (int j = 0; j < 4; j++) {
                mma16816(acc[i][j], Ah[i], Bh[j]);
                mma16816(acc[i][j], Al[i], Bh[j]);
                mma16816(acc[i][j], Ah[i], Bl[j]);
            }
    }

    // store h as fp16
    #pragma unroll
    for (int i = 0; i < 4; i++) {
        int r = row0 + mbase + i * 16 + g;
        #pragma unroll
        for (int j = 0; j < 4; j++) {
            int c = nbase + j * 8 + 2 * tq;
            *(__half2*)(g_hh + (size_t)r * DD + c) =
                __float22half2_rn(make_float2(acc[i][j][0], acc[i][j][1]));
            *(__half2*)(g_hh + (size_t)(r + 8) * DD + c) =
                __float22half2_rn(make_float2(acc[i][j][2], acc[i][j][3]));
        }
    }

    // fused rowdots
    float asv[4][2], adv[4][2];
    #pragma unroll
    for (int j = 0; j < 4; j++) {
        int c = nbase + j * 8 + 2 * tq;
        asv[j][0] = a_s[c]; asv[j][1] = a_s[c + 1];
        adv[j][0] = a_d[c]; adv[j][1] = a_d[c + 1];
    }
    __syncthreads();
    float* s_red = (float*)smem_raw;
    if (tid < 128) { s_red[tid] = 0.f; s_red[128 + tid] = 0.f; }
    __syncthreads();
    #pragma unroll
    for (int i = 0; i < 4; i++) {
        float ps0 = 0.f, pd0 = 0.f, ps1 = 0.f, pd1 = 0.f;
        #pragma unroll
        for (int j = 0; j < 4; j++) {
            ps0 += acc[i][j][0] * asv[j][0] + acc[i][j][1] * asv[j][1];
            pd0 += acc[i][j][0] * adv[j][0] + acc[i][j][1] * adv[j][1];
            ps1 += acc[i][j][2] * asv[j][0] + acc[i][j][3] * asv[j][1];
            pd1 += acc[i][j][2] * adv[j][0] + acc[i][j][3] * adv[j][1];
        }
        #pragma unroll
        for (int o = 1; o < 4; o <<= 1) {
            ps0 += __shfl_xor_sync(0xffffffffu, ps0, o);
            pd0 += __shfl_xor_sync(0xffffffffu, pd0, o);
            ps1 += __shfl_xor_sync(0xffffffffu, ps1, o);
            pd1 += __shfl_xor_sync(0xffffffffu, pd1, o);
        }
        if (tq == 0) {
            int rl = mbase + i * 16 + g;
            atomicAdd(&s_red[rl], ps0);
            atomicAdd(&s_red[128 + rl], pd0);
            atomicAdd(&s_red[rl + 8], ps1);
            atomicAdd(&s_red[128 + rl + 8], pd1);
        }
    }
    __syncthreads();
    if (tid < 128) {
        g_as[row0 + tid] = s_red[tid];
        g_ad[row0 + tid] = s_red[128 + tid];
    }
}

// ---------------- single-pass aggregate (direct exp, no max) + bias + GELU ----------------
__global__ void __launch_bounds__(256) k_agg(int l, const float* __restrict__ bias_l,
                                             float* __restrict__ outp) {
    int d = (blockIdx.x * blockDim.x + threadIdx.x) >> 5;
    int lane = threadIdx.x & 31;
    if (d >= NN) return;
    float* out = outp ? outp : g_x;

    int beg = g_rowptr[d];
    int end = g_rowptr[d + 1];
    float add = g_ad[d];
    const int4* ep = g_epk4;
    const uint2* h2 = (const uint2*)g_hh;

    float den = 0.f;
    float4 acc = make_float4(0.f, 0.f, 0.f, 0.f);

    for (int base = beg; base < end; base += 32) {
        int j = base + lane;
        float ex = 0.f;
        int s = 0;
        if (j < end) {
            int4 e = ep[j];
            s = e.x;
            int sb = (l == 0) ? e.y : (l == 1) ? e.z : e.w;
            float al = g_as[s] + add + __int_as_float(sb);
            al = al > 0.f ? al : 0.2f * al;
            ex = __expf(al);
        }
        den += ex;

        int cnt = end - base;
        if (cnt > 32) cnt = 32;
        for (int t = 0; t < cnt; t++) {
            float ext = __shfl_sync(0xffffffffu, ex, t);
            int st = __shfl_sync(0xffffffffu, s, t);
            uint2 raw = h2[(size_t)st * 32 + lane];
            float2 v0 = __half22float2(*(__half2*)&raw.x);
            float2 v1 = __half22float2(*(__half2*)&raw.y);
            acc.x = fmaf(ext, v0.x, acc.x);
            acc.y = fmaf(ext, v0.y, acc.y);
            acc.z = fmaf(ext, v1.x, acc.z);
            acc.w = fmaf(ext, v1.y, acc.w);
        }
    }
    #pragma unroll
    for (int o = 16; o; o >>= 1) den += __shfl_xor_sync(0xffffffffu, den, o);
    float r = 1.0f / den;

    float4 b4 = ((const float4*)bias_l)[lane];
    float4 o4;
    o4.x = gelu_f(fmaf(acc.x, r, b4.x));
    o4.y = gelu_f(fmaf(acc.y, r, b4.y));
    o4.z = gelu_f(fmaf(acc.z, r, b4.z));
    o4.w = gelu_f(fmaf(acc.w, r, b4.w));
    ((float4*)out)[(size_t)d * 32 + lane] = o4;
}

// ---------------- launch ----------------
extern "C" void kernel_launch(void* const* d_in, const int* in_sizes, int n_in,
                              void* d_out, int out_size) {
    const float* x    = (const float*)d_in[0];
    const int*   ei   = (const int*)d_in[1];
    const float* ea   = (const float*)d_in[2];
    const float* Ws   = (const float*)d_in[3];
    const float* a_s  = (const float*)d_in[4];
    const float* a_d  = (const float*)d_in[5];
    const float* We   = (const float*)d_in[6];
    const float* ae   = (const float*)d_in[7];
    const float* bias = (const float*)d_in[8];
    float* out = (float*)d_out;

    const int SMEM_SZ = 4 * 128 * PK * 2;  // 139264 B
    cudaFuncSetAttribute(k_gemm_tc, cudaFuncAttributeMaxDynamicSharedMemorySize, SMEM_SZ);

    k_wsplit<<<449, 256>>>(Ws, We, ae);
    k_hist<<<NE / 256, 256>>>(ei);
    k_scan256<<<256, 256>>>();
    k_scatter<<<NE / 256, 256>>>(ei, ea);
    k_selfloop<<<NN / 8, 256>>>();

    for (int l = 0; l < 3; l++) {
        const float* xin = (l == 0) ? x : nullptr;
        k_gemm_tc<<<NN / 128, 256, SMEM_SZ>>>(xin, l, a_s + l * DD, a_d + l * DD);
        float* outl = (l == 2) ? out : nullptr;
        k_agg<<<NN / 8, 256>>>(l, bias + l * DD, outl);
    }
}

// round 13
// speedup vs baseline: 1.1151x; 1.0161x over previous
#include <cuda_runtime.h>
#include <cuda_bf16.h>
#include <cuda_fp16.h>
#include <stdint.h>
#include <math.h>

#define NN 65536
#define NE 524288
#define EX (NE + NN)
#define DD 128
#define PK 136   // padded k-dim (bf16 elems); 272B rows => ldmatrix conflict-free

// ---------------- scratch (device globals: allocation-free) ----------------
__device__ __half g_hh[(size_t)NN * DD];    // 16MB: h in fp16 (agg gather path)
__device__ float g_x[(size_t)NN * DD];      // 32MB: layer activations
__device__ float g_as[NN];
__device__ float g_ad[NN];
__device__ int4  g_epk4[EX];                // packed (src, s0, s1, s2) per CSR slot
__device__ int   g_rowptr[NN + 1];
__device__ int   g_wslot[NN];
__device__ int   g_cnt[NN];
__device__ int   g_bsum[256];
__device__ float g_ve[3][32];
__device__ __nv_bfloat16 g_wh[3][DD * DD];   // W^T split hi (n-major)
__device__ __nv_bfloat16 g_wl[3][DD * DD];   // W^T split lo (n-major)

__device__ __forceinline__ float gelu_f(float x) {
    return 0.5f * x * (1.0f + erff(x * 0.7071067811865476f));
}

// ---------------- preprocessing ----------------
// blocks 0..191: split W -> bf16 hi/lo (transposed, n-major)
// block 192:     ve[l] = We[l] @ att_edge[l]
// blocks 193..448: zero cnt (+ bsum)
__global__ void k_wsplit(const float* __restrict__ Ws,
                         const float* __restrict__ We, const float* __restrict__ ae) {
    int b = blockIdx.x;
    if (b >= 193) {
        int i = (b - 193) * 256 + threadIdx.x;
        if (i < NN) g_cnt[i] = 0;
        if (i < 256) g_bsum[i] = 0;
        return;
    }
    if (b == 192) {
        int t = threadIdx.x;
        if (t < 96) {
            int l = t / 32, k = t % 32;
            const float* w = We + l * 32 * DD + k * DD;
            const float* a = ae + l * DD;
            float s = 0.f;
            #pragma unroll 8
            for (int d = 0; d < DD; d++) s += w[d] * a[d];
            g_ve[l][k] = s;
        }
        return;
    }
    int idx = b * blockDim.x + threadIdx.x;   // 3*128*128
    int l = idx >> 14;
    int rem = idx & 16383;
    int k = rem >> 7, n = rem & 127;
    float v = Ws[idx];
    __nv_bfloat16 h = __float2bfloat16_rn(v);
    float lo = v - __bfloat162float(h);
    g_wh[l][n * DD + k] = h;
    g_wl[l][n * DD + k] = __float2bfloat16_rn(lo);
}

__global__ void k_hist(const int* __restrict__ ei) {
    int e = blockIdx.x * blockDim.x + threadIdx.x;
    if (e < NE) atomicAdd(&g_cnt[ei[NE + e]], 1);
}

// ---- fused one-kernel scan over (cnt[n] + 1): publish block sums, spin, local scan ----
__global__ void __launch_bounds__(256) k_scan256() {
    __shared__ int ws[8], ws2[8], s_base;
    int b = blockIdx.x, t = threadIdx.x;
    int n = b * 256 + t;
    int lane = t & 31, w = t >> 5;
    int v = g_cnt[n] + 1;
    int x = v;
    #pragma unroll
    for (int o = 1; o < 32; o <<= 1) {
        int y = __shfl_up_sync(0xffffffffu, x, o);
        if (lane >= o) x += y;
    }
    if (lane == 31) ws[w] = x;
    __syncthreads();
    if (t < 8) {
        int s = ws[t];
        #pragma unroll
        for (int o = 1; o < 8; o <<= 1) {
            int y = __shfl_up_sync(0xffu, s, o);
            if (t >= o) s += y;
        }
        ws[t] = s;
    }
    __syncthreads();
    int intra = x - v + (w ? ws[w - 1] : 0);
    int total = ws[7];
    if (t == 0) atomicExch(&g_bsum[b], total);
    volatile int* vb = g_bsum;
    int av;
    while ((av = vb[t]) == 0) { }
    int contrib = (t < b) ? av : 0;
    #pragma unroll
    for (int o = 16; o; o >>= 1) contrib += __shfl_xor_sync(0xffffffffu, contrib, o);
    if (lane == 0) ws2[w] = contrib;
    __syncthreads();
    if (t == 0) {
        int s = 0;
        #pragma unroll
        for (int i = 0; i < 8; i++) s += ws2[i];
        s_base = s;
    }
    __syncthreads();
    int excl = s_base + intra;
    g_rowptr[n] = excl;
    g_wslot[n] = excl;
    if (n == NN - 1) g_rowptr[NN] = EX;
}

// warp handles 32 edges: coalesced 4KB attr load -> swizzled smem -> per-lane dots
__global__ void __launch_bounds__(256) k_scatter(const int* __restrict__ ei,
                                                 const float* __restrict__ ea) {
    __shared__ float sve[96];
    __shared__ __align__(16) char sbuf[8][4096];
    int tid = threadIdx.x;
    if (tid < 96) sve[tid] = ((const float*)g_ve)[tid];
    __syncthreads();
    int wid = tid >> 5, lane = tid & 31;
    int e = blockIdx.x * 256 + tid;
    int ebase = blockIdx.x * 256 + wid * 32;

    const float4* src = (const float4*)(ea + (size_t)ebase * 32);
    #pragma unroll
    for (int q = 0; q < 8; q++) {
        int idx = q * 32 + lane;
        uint32_t boff = (uint32_t)idx * 16u;
        uint32_t sw = boff ^ ((boff >> 3) & 0x70u);
        *(float4*)(sbuf[wid] + sw) = src[idx];
    }
    __syncwarp();

    float dot0 = 0.f, dot1 = 0.f, dot2 = 0.f;
    #pragma unroll
    for (int q = 0; q < 8; q++) {
        uint32_t boff = (uint32_t)lane * 128u + (uint32_t)q * 16u;
        uint32_t sw = boff ^ ((boff >> 3) & 0x70u);
        float4 v = *(const float4*)(sbuf[wid] + sw);
        const float* v0 = sve + 0 * 32 + q * 4;
        const float* v1 = sve + 1 * 32 + q * 4;
        const float* v2 = sve + 2 * 32 + q * 4;
        dot0 += v.x * v0[0] + v.y * v0[1] + v.z * v0[2] + v.w * v0[3];
        dot1 += v.x * v1[0] + v.y * v1[1] + v.z * v1[2] + v.w * v1[3];
        dot2 += v.x * v2[0] + v.y * v2[1] + v.z * v2[2] + v.w * v2[3];
    }

    int s = ei[e];
    int d = ei[NE + e];
    int p = atomicAdd(&g_wslot[d], 1);
    g_epk4[p] = make_int4(s, __float_as_int(dot0), __float_as_int(dot1), __float_as_int(dot2));
}

// ---------------- tensor-core GEMM + fused rowdots, fp16 h output (R6, proven) ----------------
__device__ __forceinline__ void mma16816(float* c, const unsigned* a, const unsigned* b) {
    asm volatile(
        "mma.sync.aligned.m16n8k16.row.col.f32.bf16.bf16.f32 "
        "{%0,%1,%2,%3},{%4,%5,%6,%7},{%8,%9},{%0,%1,%2,%3};\n"
        : "+f"(c[0]), "+f"(c[1]), "+f"(c[2]), "+f"(c[3])
        : "r"(a[0]), "r"(a[1]), "r"(a[2]), "r"(a[3]), "r"(b[0]), "r"(b[1]));
}

__device__ __forceinline__ void ldm_x4(unsigned* r, unsigned addr) {
    asm volatile("ldmatrix.sync.aligned.m8n8.x4.shared.b16 {%0,%1,%2,%3},[%4];"
                 : "=r"(r[0]), "=r"(r[1]), "=r"(r[2]), "=r"(r[3]) : "r"(addr));
}

__device__ __forceinline__ void ldm_x2(unsigned* r, unsigned addr) {
    asm volatile("ldmatrix.sync.aligned.m8n8.x2.shared.b16 {%0,%1},[%2];"
                 : "=r"(r[0]), "=r"(r[1]) : "r"(addr));
}

extern __shared__ char smem_raw[];

__global__ void __launch_bounds__(256) k_gemm_tc(const float* __restrict__ Ain, int l,
                                                 const float* __restrict__ a_s,
                                                 const float* __restrict__ a_d) {
    const float* A = Ain ? Ain : g_x;
    __nv_bfloat16* sAh = (__nv_bfloat16*)smem_raw;
    __nv_bfloat16* sAl = sAh + 128 * PK;
    __nv_bfloat16* sBh = sAl + 128 * PK;
    __nv_bfloat16* sBl = sBh + 128 * PK;

    int tid = threadIdx.x;
    int row0 = blockIdx.x * 128;

    {
        const float4* A4 = (const float4*)(A + (size_t)row0 * DD);
        #pragma unroll
        for (int it = 0; it < 16; it++) {
            int idx = it * 256 + tid;
            int r = idx >> 5;
            int c = (idx & 31) << 2;
            float4 v = A4[idx];
            __nv_bfloat16 h0 = __float2bfloat16_rn(v.x), h1 = __float2bfloat16_rn(v.y);
            __nv_bfloat16 h2 = __float2bfloat16_rn(v.z), h3 = __float2bfloat16_rn(v.w);
            __nv_bfloat162 ha, hb, la, lb;
            ha.x = h0; ha.y = h1; hb.x = h2; hb.y = h3;
            la = __floats2bfloat162_rn(v.x - __bfloat162float(h0), v.y - __bfloat162float(h1));
            lb = __floats2bfloat162_rn(v.z - __bfloat162float(h2), v.w - __bfloat162float(h3));
            unsigned* dh = (unsigned*)(sAh + r * PK + c);
            unsigned* dl = (unsigned*)(sAl + r * PK + c);
            dh[0] = *(unsigned*)&ha; dh[1] = *(unsigned*)&hb;
            dl[0] = *(unsigned*)&la; dl[1] = *(unsigned*)&lb;
        }
    }
    {
        const uint4* wh4 = (const uint4*)g_wh[l];
        const uint4* wl4 = (const uint4*)g_wl[l];
        #pragma unroll
        for (int it = 0; it < 8; it++) {
            int idx = it * 256 + tid;
            int n = idx >> 4;
            int kc = idx & 15;
            ((uint4*)(sBh + n * PK))[kc] = wh4[idx];
            ((uint4*)(sBl + n * PK))[kc] = wl4[idx];
        }
    }
    __syncthreads();

    int wid = tid >> 5, lane = tid & 31;
    int g = lane >> 2, tq = lane & 3;
    int wm = wid >> 2, wn = wid & 3;
    int mbase = wm * 64, nbase = wn * 32;

    unsigned baseAh, baseAl, baseBh, baseBl;
    {
        int aoff = ((mbase + (lane & 15)) * PK + ((lane >> 4) << 3)) * 2;
        baseAh = (unsigned)__cvta_generic_to_shared(sAh) + aoff;
        baseAl = (unsigned)__cvta_generic_to_shared(sAl) + aoff;
        int boff = ((nbase + (lane & 7)) * PK + (((lane >> 3) & 1) << 3)) * 2;
        baseBh = (unsigned)__cvta_generic_to_shared(sBh) + boff;
        baseBl = (unsigned)__cvta_generic_to_shared(sBl) + boff;
    }

    float acc[4][4][4];
    #pragma unroll
    for (int i = 0; i < 4; i++)
        #pragma unroll
        for (int j = 0; j < 4; j++)
            #pragma unroll
            for (int q = 0; q < 4; q++) acc[i][j][q] = 0.f;

    #pragma unroll
    for (int kk = 0; kk < 8; kk++) {
        unsigned kb = kk * 32;
        unsigned Ah[4][4], Al[4][4], Bh[4][2], Bl[4][2];
        #pragma unroll
        for (int i = 0; i < 4; i++) {
            unsigned off = (unsigned)(i * 16 * PK * 2) + kb;
            ldm_x4(Ah[i], baseAh + off);
            ldm_x4(Al[i], baseAl + off);
        }
        #pragma unroll
        for (int j = 0; j < 4; j++) {
            unsigned off = (unsigned)(j * 8 * PK * 2) + kb;
            ldm_x2(Bh[j], baseBh + off);
            ldm_x2(Bl[j], baseBl + off);
        }
        #pragma unroll
        for (int i = 0; i < 4; i++)
            #pragma unroll
            for (int j = 0; j < 4; j++) {
                mma16816(acc[i][j], Ah[i], Bh[j]);
                mma16816(acc[i][j], Al[i], Bh[j]);
                mma16816(acc[i][j], Ah[i], Bl[j]);
            }
    }

    // store h as fp16
    #pragma unroll
    for (int i = 0; i < 4; i++) {
        int r = row0 + mbase + i * 16 + g;
        #pragma unroll
        for (int j = 0; j < 4; j++) {
            int c = nbase + j * 8 + 2 * tq;
            *(__half2*)(g_hh + (size_t)r * DD + c) =
                __float22half2_rn(make_float2(acc[i][j][0], acc[i][j][1]));
            *(__half2*)(g_hh + (size_t)(r + 8) * DD + c) =
                __float22half2_rn(make_float2(acc[i][j][2], acc[i][j][3]));
        }
    }

    // fused rowdots
    float asv[4][2], adv[4][2];
    #pragma unroll
    for (int j = 0; j < 4; j++) {
        int c = nbase + j * 8 + 2 * tq;
        asv[j][0] = a_s[c]; asv[j][1] = a_s[c + 1];
        adv[j][0] = a_d[c]; adv[j][1] = a_d[c + 1];
    }
    __syncthreads();
    float* s_red = (float*)smem_raw;
    if (tid < 128) { s_red[tid] = 0.f; s_red[128 + tid] = 0.f; }
    __syncthreads();
    #pragma unroll
    for (int i = 0; i < 4; i++) {
        float ps0 = 0.f, pd0 = 0.f, ps1 = 0.f, pd1 = 0.f;
        #pragma unroll
        for (int j = 0; j < 4; j++) {
            ps0 += acc[i][j][0] * asv[j][0] + acc[i][j][1] * asv[j][1];
            pd0 += acc[i][j][0] * adv[j][0] + acc[i][j][1] * adv[j][1];
            ps1 += acc[i][j][2] * asv[j][0] + acc[i][j][3] * asv[j][1];
            pd1 += acc[i][j][2] * adv[j][0] + acc[i][j][3] * adv[j][1];
        }
        #pragma unroll
        for (int o = 1; o < 4; o <<= 1) {
            ps0 += __shfl_xor_sync(0xffffffffu, ps0, o);
            pd0 += __shfl_xor_sync(0xffffffffu, pd0, o);
            ps1 += __shfl_xor_sync(0xffffffffu, ps1, o);
            pd1 += __shfl_xor_sync(0xffffffffu, pd1, o);
        }
        if (tq == 0) {
            int rl = mbase + i * 16 + g;
            atomicAdd(&s_red[rl], ps0);
            atomicAdd(&s_red[128 + rl], pd0);
            atomicAdd(&s_red[rl + 8], ps1);
            atomicAdd(&s_red[128 + rl + 8], pd1);
        }
    }
    __syncthreads();
    if (tid < 128) {
        g_as[row0 + tid] = s_red[tid];
        g_ad[row0 + tid] = s_red[128 + tid];
    }
}

// ------- single-pass aggregate + inline self-loop + bias + GELU (warp/node) -------
__global__ void __launch_bounds__(256) k_agg(int l, const float* __restrict__ bias_l,
                                             float* __restrict__ outp) {
    int d = (blockIdx.x * blockDim.x + threadIdx.x) >> 5;
    int lane = threadIdx.x & 31;
    if (d >= NN) return;
    float* out = outp ? outp : g_x;

    int beg = g_rowptr[d];
    int endE = g_rowptr[d + 1] - 1;   // real edges in [beg, endE); self-loop slot at endE
    float add = g_ad[d];
    float asd = g_as[d];
    const int4* ep = g_epk4;
    const uint2* h2 = (const uint2*)g_hh;

    float den = 0.f;
    float ssum = 0.f;                 // raw score sum for self-loop fill
    float4 acc = make_float4(0.f, 0.f, 0.f, 0.f);

    for (int base = beg; base < endE; base += 32) {
        int j = base + lane;
        float ex = 0.f;
        int s = 0;
        if (j < endE) {
            int4 e = ep[j];
            s = e.x;
            int sbi = (l == 0) ? e.y : (l == 1) ? e.z : e.w;
            float sc = __int_as_float(sbi);
            ssum += sc;
            float al = g_as[s] + add + sc;
            al = al > 0.f ? al : 0.2f * al;
            ex = __expf(al);
        }
        den += ex;

        int cnt = endE - base;
        if (cnt > 32) cnt = 32;
        int t = 0;
        for (; t + 2 <= cnt; t += 2) {
            float e0 = __shfl_sync(0xffffffffu, ex, t);
            float e1 = __shfl_sync(0xffffffffu, ex, t + 1);
            int s0 = __shfl_sync(0xffffffffu, s, t);
            int s1 = __shfl_sync(0xffffffffu, s, t + 1);
            uint2 r0 = h2[(size_t)s0 * 32 + lane];
            uint2 r1 = h2[(size_t)s1 * 32 + lane];
            float2 a0 = __half22float2(*(__half2*)&r0.x);
            float2 b0 = __half22float2(*(__half2*)&r0.y);
            float2 a1 = __half22float2(*(__half2*)&r1.x);
            float2 b1 = __half22float2(*(__half2*)&r1.y);
            acc.x = fmaf(e0, a0.x, fmaf(e1, a1.x, acc.x));
            acc.y = fmaf(e0, a0.y, fmaf(e1, a1.y, acc.y));
            acc.z = fmaf(e0, b0.x, fmaf(e1, b1.x, acc.z));
            acc.w = fmaf(e0, b0.y, fmaf(e1, b1.y, acc.w));
        }
        if (t < cnt) {
            float e0 = __shfl_sync(0xffffffffu, ex, t);
            int s0 = __shfl_sync(0xffffffffu, s, t);
            uint2 r0 = h2[(size_t)s0 * 32 + lane];
            float2 a0 = __half22float2(*(__half2*)&r0.x);
            float2 b0 = __half22float2(*(__half2*)&r0.y);
            acc.x = fmaf(e0, a0.x, acc.x);
            acc.y = fmaf(e0, a0.y, acc.y);
            acc.z = fmaf(e0, b0.x, acc.z);
            acc.w = fmaf(e0, b0.y, acc.w);
        }
    }
    #pragma unroll
    for (int o = 16; o; o >>= 1) {
        den += __shfl_xor_sync(0xffffffffu, den, o);
        ssum += __shfl_xor_sync(0xffffffffu, ssum, o);
    }

    // self-loop: score = mean of incoming scores (0 if none)
    float cf = fmaxf((float)(endE - beg), 1.0f);
    float als = asd + add + ssum / cf;
    als = als > 0.f ? als : 0.2f * als;
    float exs = __expf(als);
    den += exs;
    {
        uint2 raw = h2[(size_t)d * 32 + lane];
        float2 v0 = __half22float2(*(__half2*)&raw.x);
        float2 v1 = __half22float2(*(__half2*)&raw.y);
        acc.x = fmaf(exs, v0.x, acc.x);
        acc.y = fmaf(exs, v0.y, acc.y);
        acc.z = fmaf(exs, v1.x, acc.z);
        acc.w = fmaf(exs, v1.y, acc.w);
    }

    float r = 1.0f / den;
    float4 b4 = ((const float4*)bias_l)[lane];
    float4 o4;
    o4.x = gelu_f(fmaf(acc.x, r, b4.x));
    o4.y = gelu_f(fmaf(acc.y, r, b4.y));
    o4.z = gelu_f(fmaf(acc.z, r, b4.z));
    o4.w = gelu_f(fmaf(acc.w, r, b4.w));
    ((float4*)out)[(size_t)d * 32 + lane] = o4;
}

// ---------------- launch ----------------
extern "C" void kernel_launch(void* const* d_in, const int* in_sizes, int n_in,
                              void* d_out, int out_size) {
    const float* x    = (const float*)d_in[0];
    const int*   ei   = (const int*)d_in[1];
    const float* ea   = (const float*)d_in[2];
    const float* Ws   = (const float*)d_in[3];
    const float* a_s  = (const float*)d_in[4];
    const float* a_d  = (const float*)d_in[5];
    const float* We   = (const float*)d_in[6];
    const float* ae   = (const float*)d_in[7];
    const float* bias = (const float*)d_in[8];
    float* out = (float*)d_out;

    const int SMEM_SZ = 4 * 128 * PK * 2;  // 139264 B
    cudaFuncSetAttribute(k_gemm_tc, cudaFuncAttributeMaxDynamicSharedMemorySize, SMEM_SZ);

    k_wsplit<<<449, 256>>>(Ws, We, ae);
    k_hist<<<NE / 256, 256>>>(ei);
    k_scan256<<<256, 256>>>();
    k_scatter<<<NE / 256, 256>>>(ei, ea);

    for (int l = 0; l < 3; l++) {
        const float* xin = (l == 0) ? x : nullptr;
        k_gemm_tc<<<NN / 128, 256, SMEM_SZ>>>(xin, l, a_s + l * DD, a_d + l * DD);
        float* outl = (l == 2) ? out : nullptr;
        k_agg<<<NN / 8, 256>>>(l, bias + l * DD, outl);
    }
}